// round 2
// baseline (speedup 1.0000x reference)
#include <cuda_runtime.h>
#include <math.h>

// Problem constants (fixed by the reference)
#define Hdim   128
#define NINdim 384
#define CIN    512           // Hdim + NINdim
#define KNB    48            // neighbors per node
#define FFdim  512
#define NTHREADS 256

// ---------------- shared memory layout (in floats) ----------------
// Phase A/B:   sX  [48][512]        @ 0       (24576)
// Phase B:     sW1t[64][132]        @ 30720   (8448)   (k-tile of W1, transposed, pad 4)
// Phase B out: sY  [48][128]        @ 24576   (6144)
// Phase C:     sW2t[128][132]       @ 0       (16896)  (reuses sX)
// Phase C out: sY2 [48][128]        @ 16896   (6144)
// Phase D:     sW3t[128][132]       @ 0       (16896)
// Phase D/E small region (reuses sY area @24576):
//   sRed[8][128] @24576, sVecA[128] @25600, sH[128] @25728,
//   sF[512] @25856, sOutPart[2][128] @26368, sStats[8] @26624
// Total = 39168 floats = 156672 bytes
#define SMEM_FLOATS 39168
#define SMEM_BYTES  (SMEM_FLOATS * 4)

#define OFF_X     0
#define OFF_W2    0
#define OFF_W3    0
#define OFF_Y2    16896
#define OFF_Y     24576
#define OFF_RED   24576
#define OFF_VECA  25600
#define OFF_H     25728
#define OFF_F     25856
#define OFF_OPART 26368
#define OFF_STATS 26624
#define OFF_W1    30720

#define WPAD 132   // padded row stride for transposed weight tiles

__device__ __forceinline__ float gelu_erf(float x) {
    return 0.5f * x * (1.0f + erff(x * 0.70710678118654752440f));
}

// warp-0 block reduction over a 128-float vector in smem -> mean, rstd into sStats[o], sStats[o+1]
__device__ __forceinline__ void ln_stats(const float* v, float* sStats, int o, int tid) {
    if (tid < 32) {
        float s = 0.f, s2 = 0.f;
        #pragma unroll
        for (int i = 0; i < 4; ++i) {
            float x = v[tid + i * 32];
            s += x; s2 += x * x;
        }
        #pragma unroll
        for (int off = 16; off > 0; off >>= 1) {
            s  += __shfl_xor_sync(0xffffffffu, s,  off);
            s2 += __shfl_xor_sync(0xffffffffu, s2, off);
        }
        if (tid == 0) {
            float mean = s * (1.0f / 128.0f);
            float var  = s2 * (1.0f / 128.0f) - mean * mean;
            sStats[o]     = mean;
            sStats[o + 1] = rsqrtf(var + 1e-5f);
        }
    }
}

__global__ void __launch_bounds__(NTHREADS, 1)
decoder_layer_kernel(
    const float* __restrict__ h_V, const float* __restrict__ h_E,
    const float* __restrict__ mask_V, const float* __restrict__ mask_attend,
    const float* __restrict__ W1_w, const float* __restrict__ W1_b,
    const float* __restrict__ W2_w, const float* __restrict__ W2_b,
    const float* __restrict__ W3_w, const float* __restrict__ W3_b,
    const float* __restrict__ ln1_g, const float* __restrict__ ln1_b,
    const float* __restrict__ ln2_g, const float* __restrict__ ln2_b,
    const float* __restrict__ Win_w, const float* __restrict__ Win_b,
    const float* __restrict__ Wout_w, const float* __restrict__ Wout_b,
    float* __restrict__ out)
{
    extern __shared__ float sm[];
    const int tid = threadIdx.x;
    const int tx  = tid & 31;          // n-dim lane (float4 column index)
    const int ty  = tid >> 5;          // 0..7
    const int m0  = ty * 6;            // 6 edge-rows per thread group
    const int ng  = blockIdx.x;        // flat node id (b*N + n), 0..4095

    float* sX = sm + OFF_X;

    // ---------------- Phase A: build edge inputs [48][512] ----------------
    {
        const float4* hv4 = (const float4*)(h_V + (size_t)ng * Hdim);   // 32 f4
        #pragma unroll
        for (int it = 0; it < 6; ++it) {                 // 48*32 = 1536 f4
            int idx = it * NTHREADS + tid;
            int m = idx >> 5, q = idx & 31;
            ((float4*)sX)[m * 128 + q] = hv4[q];
        }
        const float4* he4 = (const float4*)(h_E + (size_t)ng * (KNB * NINdim));
        #pragma unroll
        for (int it = 0; it < 18; ++it) {                // 48*96 = 4608 f4
            int idx = it * NTHREADS + tid;
            int m = idx / 96, q = idx - m * 96;
            ((float4*)sX)[m * 128 + 32 + q] = he4[idx];
        }
    }
    __syncthreads();

    float acc[6][4];

    // ---------------- Phase B: Y1 = gelu(X @ W1^T + b1) ----------------
    #pragma unroll
    for (int j = 0; j < 6; ++j)
        #pragma unroll
        for (int c = 0; c < 4; ++c) acc[j][c] = 0.f;

    {
        float* sW = sm + OFF_W1;
        const float4* W1f4 = (const float4*)W1_w;   // [128][128] f4 (row = 512 floats)
        for (int kt = 0; kt < 8; ++kt) {
            const int k0 = kt * 64;
            // stage transposed tile: sW[kk][n] = W1[n][k0+kk]
            #pragma unroll
            for (int it = 0; it < 8; ++it) {            // 2048 f4
                int idx = it * NTHREADS + tid;
                int n = idx >> 4, q = idx & 15;
                float4 w = W1f4[n * 128 + (k0 >> 2) + q];
                int kk = q * 4;
                sW[(kk + 0) * WPAD + n] = w.x;
                sW[(kk + 1) * WPAD + n] = w.y;
                sW[(kk + 2) * WPAD + n] = w.z;
                sW[(kk + 3) * WPAD + n] = w.w;
            }
            __syncthreads();
            #pragma unroll 8
            for (int kk = 0; kk < 64; ++kk) {
                float4 w = *(const float4*)(sW + kk * WPAD + (tx << 2));
                #pragma unroll
                for (int j = 0; j < 6; ++j) {
                    float xv = sX[(m0 + j) * CIN + k0 + kk];
                    acc[j][0] = fmaf(xv, w.x, acc[j][0]);
                    acc[j][1] = fmaf(xv, w.y, acc[j][1]);
                    acc[j][2] = fmaf(xv, w.z, acc[j][2]);
                    acc[j][3] = fmaf(xv, w.w, acc[j][3]);
                }
            }
            __syncthreads();
        }
    }

    // bias + gelu -> sY, and stage W2 transposed into sX region
    {
        float* sY = sm + OFF_Y;
        float4 bv = ((const float4*)W1_b)[tx];
        #pragma unroll
        for (int j = 0; j < 6; ++j) {
            float4 r;
            r.x = gelu_erf(acc[j][0] + bv.x);
            r.y = gelu_erf(acc[j][1] + bv.y);
            r.z = gelu_erf(acc[j][2] + bv.z);
            r.w = gelu_erf(acc[j][3] + bv.w);
            ((float4*)(sY + (m0 + j) * 128))[tx] = r;
        }
        float* sW2 = sm + OFF_W2;
        const float4* W2f4 = (const float4*)W2_w;   // row = 128 floats = 32 f4
        #pragma unroll
        for (int it = 0; it < 16; ++it) {            // 4096 f4
            int idx = it * NTHREADS + tid;
            int n = idx >> 5, q = idx & 31;
            float4 w = W2f4[n * 32 + q];
            int kk = q * 4;
            sW2[(kk + 0) * WPAD + n] = w.x;
            sW2[(kk + 1) * WPAD + n] = w.y;
            sW2[(kk + 2) * WPAD + n] = w.z;
            sW2[(kk + 3) * WPAD + n] = w.w;
        }
    }
    __syncthreads();

    // ---------------- Phase C: Y2 = gelu(Y1 @ W2^T + b2) ----------------
    #pragma unroll
    for (int j = 0; j < 6; ++j)
        #pragma unroll
        for (int c = 0; c < 4; ++c) acc[j][c] = 0.f;
    {
        const float* sY = sm + OFF_Y;
        const float* sW2 = sm + OFF_W2;
        #pragma unroll 8
        for (int kk = 0; kk < 128; ++kk) {
            float4 w = *(const float4*)(sW2 + kk * WPAD + (tx << 2));
            #pragma unroll
            for (int j = 0; j < 6; ++j) {
                float xv = sY[(m0 + j) * 128 + kk];
                acc[j][0] = fmaf(xv, w.x, acc[j][0]);
                acc[j][1] = fmaf(xv, w.y, acc[j][1]);
                acc[j][2] = fmaf(xv, w.z, acc[j][2]);
                acc[j][3] = fmaf(xv, w.w, acc[j][3]);
            }
        }
    }
    {
        float* sY2 = sm + OFF_Y2;
        float4 bv = ((const float4*)W2_b)[tx];
        #pragma unroll
        for (int j = 0; j < 6; ++j) {
            float4 r;
            r.x = gelu_erf(acc[j][0] + bv.x);
            r.y = gelu_erf(acc[j][1] + bv.y);
            r.z = gelu_erf(acc[j][2] + bv.z);
            r.w = gelu_erf(acc[j][3] + bv.w);
            ((float4*)(sY2 + (m0 + j) * 128))[tx] = r;
        }
    }
    __syncthreads();

    // stage W3 transposed (overwrites W2 region)
    {
        float* sW3 = sm + OFF_W3;
        const float4* W3f4 = (const float4*)W3_w;
        #pragma unroll
        for (int it = 0; it < 16; ++it) {
            int idx = it * NTHREADS + tid;
            int n = idx >> 5, q = idx & 31;
            float4 w = W3f4[n * 32 + q];
            int kk = q * 4;
            sW3[(kk + 0) * WPAD + n] = w.x;
            sW3[(kk + 1) * WPAD + n] = w.y;
            sW3[(kk + 2) * WPAD + n] = w.z;
            sW3[(kk + 3) * WPAD + n] = w.w;
        }
    }
    __syncthreads();

    // ---------------- Phase D: msg = Y2 @ W3^T + b3 ; masked sum over edges ----------------
    #pragma unroll
    for (int j = 0; j < 6; ++j)
        #pragma unroll
        for (int c = 0; c < 4; ++c) acc[j][c] = 0.f;
    {
        const float* sY2 = sm + OFF_Y2;
        const float* sW3 = sm + OFF_W3;
        #pragma unroll 8
        for (int kk = 0; kk < 128; ++kk) {
            float4 w = *(const float4*)(sW3 + kk * WPAD + (tx << 2));
            #pragma unroll
            for (int j = 0; j < 6; ++j) {
                float xv = sY2[(m0 + j) * 128 + kk];
                acc[j][0] = fmaf(xv, w.x, acc[j][0]);
                acc[j][1] = fmaf(xv, w.y, acc[j][1]);
                acc[j][2] = fmaf(xv, w.z, acc[j][2]);
                acc[j][3] = fmaf(xv, w.w, acc[j][3]);
            }
        }
    }
    {
        float* sRed = sm + OFF_RED;
        float4 bv = ((const float4*)W3_b)[tx];
        float p0 = 0.f, p1 = 0.f, p2 = 0.f, p3 = 0.f;
        #pragma unroll
        for (int j = 0; j < 6; ++j) {
            float ma = mask_attend[(size_t)ng * KNB + m0 + j];
            p0 = fmaf(ma, acc[j][0] + bv.x, p0);
            p1 = fmaf(ma, acc[j][1] + bv.y, p1);
            p2 = fmaf(ma, acc[j][2] + bv.z, p2);
            p3 = fmaf(ma, acc[j][3] + bv.w, p3);
        }
        float4 pv; pv.x = p0; pv.y = p1; pv.z = p2; pv.w = p3;
        ((float4*)(sRed + ty * 128))[tx] = pv;
    }
    __syncthreads();

    float* sVecA  = sm + OFF_VECA;
    float* sH     = sm + OFF_H;
    float* sF     = sm + OFF_F;
    float* sOPart = sm + OFF_OPART;
    float* sStats = sm + OFF_STATS;

    // dh = sum/30 ; pre-LN1 value x = h_V + dh
    if (tid < 128) {
        const float* sRed = sm + OFF_RED;
        float dh = 0.f;
        #pragma unroll
        for (int g = 0; g < 8; ++g) dh += sRed[g * 128 + tid];
        dh *= (1.0f / 30.0f);
        sVecA[tid] = h_V[(size_t)ng * Hdim + tid] + dh;
    }
    __syncthreads();
    ln_stats(sVecA, sStats, 0, tid);
    __syncthreads();
    if (tid < 128) {
        float hh = (sVecA[tid] - sStats[0]) * sStats[1] * ln1_g[tid] + ln1_b[tid];
        sH[tid] = hh;
    }
    __syncthreads();

    // ---------------- Phase E: FFN ----------------
    #pragma unroll
    for (int r = 0; r < 2; ++r) {
        int f = tid + r * NTHREADS;          // 0..511
        float a = Win_b[f];
        const float4* wrow = (const float4*)(Win_w + (size_t)f * 128);
        #pragma unroll
        for (int q = 0; q < 32; ++q) {
            float4 w = wrow[q];
            a = fmaf(w.x, sH[q * 4 + 0], a);
            a = fmaf(w.y, sH[q * 4 + 1], a);
            a = fmaf(w.z, sH[q * 4 + 2], a);
            a = fmaf(w.w, sH[q * 4 + 3], a);
        }
        sF[f] = gelu_erf(a);
    }
    __syncthreads();

    {
        int n = tid & 127, half = tid >> 7;
        const float4* wrow = (const float4*)(Wout_w + (size_t)n * FFdim + half * 256);
        const float* sFh = sF + half * 256;
        float a = 0.f;
        #pragma unroll
        for (int q = 0; q < 64; ++q) {
            float4 w = wrow[q];
            a = fmaf(w.x, sFh[q * 4 + 0], a);
            a = fmaf(w.y, sFh[q * 4 + 1], a);
            a = fmaf(w.z, sFh[q * 4 + 2], a);
            a = fmaf(w.w, sFh[q * 4 + 3], a);
        }
        sOPart[half * 128 + n] = a;
    }
    __syncthreads();

    if (tid < 128) {
        float dh2 = sOPart[tid] + sOPart[128 + tid] + Wout_b[tid];
        sVecA[tid] = sH[tid] + dh2;
    }
    __syncthreads();
    ln_stats(sVecA, sStats, 2, tid);
    __syncthreads();
    if (tid < 128) {
        float v = (sVecA[tid] - sStats[2]) * sStats[3] * ln2_g[tid] + ln2_b[tid];
        out[(size_t)ng * Hdim + tid] = mask_V[ng] * v;
    }
}

extern "C" void kernel_launch(void* const* d_in, const int* in_sizes, int n_in,
                              void* d_out, int out_size) {
    const float* h_V         = (const float*)d_in[0];
    const float* h_E         = (const float*)d_in[1];
    const float* mask_V      = (const float*)d_in[2];
    const float* mask_attend = (const float*)d_in[3];
    const float* W1_w        = (const float*)d_in[4];
    const float* W1_b        = (const float*)d_in[5];
    const float* W2_w        = (const float*)d_in[6];
    const float* W2_b        = (const float*)d_in[7];
    const float* W3_w        = (const float*)d_in[8];
    const float* W3_b        = (const float*)d_in[9];
    const float* ln1_g       = (const float*)d_in[10];
    const float* ln1_b       = (const float*)d_in[11];
    const float* ln2_g       = (const float*)d_in[12];
    const float* ln2_b       = (const float*)d_in[13];
    const float* Win_w       = (const float*)d_in[14];
    const float* Win_b       = (const float*)d_in[15];
    const float* Wout_w      = (const float*)d_in[16];
    const float* Wout_b      = (const float*)d_in[17];

    int nodes = in_sizes[0] / Hdim;   // B*N = 4096

    cudaFuncSetAttribute(decoder_layer_kernel,
                         cudaFuncAttributeMaxDynamicSharedMemorySize, SMEM_BYTES);

    decoder_layer_kernel<<<nodes, NTHREADS, SMEM_BYTES>>>(
        h_V, h_E, mask_V, mask_attend,
        W1_w, W1_b, W2_w, W2_b, W3_w, W3_b,
        ln1_g, ln1_b, ln2_g, ln2_b,
        Win_w, Win_b, Wout_w, Wout_b,
        (float*)d_out);
}

// round 3
// speedup vs baseline: 1.0003x; 1.0003x over previous
#include <cuda_runtime.h>
#include <math.h>

// Problem constants (fixed by the reference)
#define Hdim   128
#define NINdim 384
#define CIN    512           // Hdim + NINdim
#define KNB    48            // neighbors per node
#define FFdim  512
#define NTHREADS 256

// ---------------- shared memory layout (in floats) ----------------
// Phase A/B:   sX  [48][512]        @ 0       (24576)
// Phase B:     sW1t[64][132]        @ 30720   (8448)   (k-tile of W1, transposed, pad 4)
// Phase B out: sY  [48][128]        @ 24576   (6144)
// Phase C:     sW2t[128][132]       @ 0       (16896)  (reuses sX)
// Phase C out: sY2 [48][128]        @ 16896   (6144)
// Phase D:     sW3t[128][132]       @ 0       (16896)
// Phase D/E small region (reuses sY area @24576):
//   sRed[8][128] @24576, sVecA[128] @25600, sH[128] @25728,
//   sF[512] @25856, sOutPart[2][128] @26368, sStats[8] @26624
// Total = 39168 floats = 156672 bytes
#define SMEM_FLOATS 39168
#define SMEM_BYTES  (SMEM_FLOATS * 4)

#define OFF_X     0
#define OFF_W2    0
#define OFF_W3    0
#define OFF_Y2    16896
#define OFF_Y     24576
#define OFF_RED   24576
#define OFF_VECA  25600
#define OFF_H     25728
#define OFF_F     25856
#define OFF_OPART 26368
#define OFF_STATS 26624
#define OFF_W1    30720

#define WPAD 132   // padded row stride for transposed weight tiles

__device__ __forceinline__ float gelu_erf(float x) {
    return 0.5f * x * (1.0f + erff(x * 0.70710678118654752440f));
}

// warp-0 block reduction over a 128-float vector in smem -> mean, rstd into sStats[o], sStats[o+1]
__device__ __forceinline__ void ln_stats(const float* v, float* sStats, int o, int tid) {
    if (tid < 32) {
        float s = 0.f, s2 = 0.f;
        #pragma unroll
        for (int i = 0; i < 4; ++i) {
            float x = v[tid + i * 32];
            s += x; s2 += x * x;
        }
        #pragma unroll
        for (int off = 16; off > 0; off >>= 1) {
            s  += __shfl_xor_sync(0xffffffffu, s,  off);
            s2 += __shfl_xor_sync(0xffffffffu, s2, off);
        }
        if (tid == 0) {
            float mean = s * (1.0f / 128.0f);
            float var  = s2 * (1.0f / 128.0f) - mean * mean;
            sStats[o]     = mean;
            sStats[o + 1] = rsqrtf(var + 1e-5f);
        }
    }
}

__global__ void __launch_bounds__(NTHREADS, 1)
decoder_layer_kernel(
    const float* __restrict__ h_V, const float* __restrict__ h_E,
    const float* __restrict__ mask_V, const float* __restrict__ mask_attend,
    const float* __restrict__ W1_w, const float* __restrict__ W1_b,
    const float* __restrict__ W2_w, const float* __restrict__ W2_b,
    const float* __restrict__ W3_w, const float* __restrict__ W3_b,
    const float* __restrict__ ln1_g, const float* __restrict__ ln1_b,
    const float* __restrict__ ln2_g, const float* __restrict__ ln2_b,
    const float* __restrict__ Win_w, const float* __restrict__ Win_b,
    const float* __restrict__ Wout_w, const float* __restrict__ Wout_b,
    float* __restrict__ out)
{
    extern __shared__ float sm[];
    const int tid = threadIdx.x;
    const int tx  = tid & 31;          // n-dim lane (float4 column index)
    const int ty  = tid >> 5;          // 0..7
    const int m0  = ty * 6;            // 6 edge-rows per thread group
    const int ng  = blockIdx.x;        // flat node id (b*N + n), 0..4095

    float* sX = sm + OFF_X;

    // ---------------- Phase A: build edge inputs [48][512] ----------------
    {
        const float4* hv4 = (const float4*)(h_V + (size_t)ng * Hdim);   // 32 f4
        #pragma unroll
        for (int it = 0; it < 6; ++it) {                 // 48*32 = 1536 f4
            int idx = it * NTHREADS + tid;
            int m = idx >> 5, q = idx & 31;
            ((float4*)sX)[m * 128 + q] = hv4[q];
        }
        const float4* he4 = (const float4*)(h_E + (size_t)ng * (KNB * NINdim));
        #pragma unroll
        for (int it = 0; it < 18; ++it) {                // 48*96 = 4608 f4
            int idx = it * NTHREADS + tid;
            int m = idx / 96, q = idx - m * 96;
            ((float4*)sX)[m * 128 + 32 + q] = he4[idx];
        }
    }
    __syncthreads();

    float acc[6][4];

    // ---------------- Phase B: Y1 = gelu(X @ W1^T + b1) ----------------
    #pragma unroll
    for (int j = 0; j < 6; ++j)
        #pragma unroll
        for (int c = 0; c < 4; ++c) acc[j][c] = 0.f;

    {
        float* sW = sm + OFF_W1;
        const float4* W1f4 = (const float4*)W1_w;   // [128][128] f4 (row = 512 floats)
        for (int kt = 0; kt < 8; ++kt) {
            const int k0 = kt * 64;
            // stage transposed tile: sW[kk][n] = W1[n][k0+kk]
            #pragma unroll
            for (int it = 0; it < 8; ++it) {            // 2048 f4
                int idx = it * NTHREADS + tid;
                int n = idx >> 4, q = idx & 15;
                float4 w = W1f4[n * 128 + (k0 >> 2) + q];
                int kk = q * 4;
                sW[(kk + 0) * WPAD + n] = w.x;
                sW[(kk + 1) * WPAD + n] = w.y;
                sW[(kk + 2) * WPAD + n] = w.z;
                sW[(kk + 3) * WPAD + n] = w.w;
            }
            __syncthreads();
            #pragma unroll 8
            for (int kk = 0; kk < 64; ++kk) {
                float4 w = *(const float4*)(sW + kk * WPAD + (tx << 2));
                #pragma unroll
                for (int j = 0; j < 6; ++j) {
                    float xv = sX[(m0 + j) * CIN + k0 + kk];
                    acc[j][0] = fmaf(xv, w.x, acc[j][0]);
                    acc[j][1] = fmaf(xv, w.y, acc[j][1]);
                    acc[j][2] = fmaf(xv, w.z, acc[j][2]);
                    acc[j][3] = fmaf(xv, w.w, acc[j][3]);
                }
            }
            __syncthreads();
        }
    }

    // bias + gelu -> sY, and stage W2 transposed into sX region
    {
        float* sY = sm + OFF_Y;
        float4 bv = ((const float4*)W1_b)[tx];
        #pragma unroll
        for (int j = 0; j < 6; ++j) {
            float4 r;
            r.x = gelu_erf(acc[j][0] + bv.x);
            r.y = gelu_erf(acc[j][1] + bv.y);
            r.z = gelu_erf(acc[j][2] + bv.z);
            r.w = gelu_erf(acc[j][3] + bv.w);
            ((float4*)(sY + (m0 + j) * 128))[tx] = r;
        }
        float* sW2 = sm + OFF_W2;
        const float4* W2f4 = (const float4*)W2_w;   // row = 128 floats = 32 f4
        #pragma unroll
        for (int it = 0; it < 16; ++it) {            // 4096 f4
            int idx = it * NTHREADS + tid;
            int n = idx >> 5, q = idx & 31;
            float4 w = W2f4[n * 32 + q];
            int kk = q * 4;
            sW2[(kk + 0) * WPAD + n] = w.x;
            sW2[(kk + 1) * WPAD + n] = w.y;
            sW2[(kk + 2) * WPAD + n] = w.z;
            sW2[(kk + 3) * WPAD + n] = w.w;
        }
    }
    __syncthreads();

    // ---------------- Phase C: Y2 = gelu(Y1 @ W2^T + b2) ----------------
    #pragma unroll
    for (int j = 0; j < 6; ++j)
        #pragma unroll
        for (int c = 0; c < 4; ++c) acc[j][c] = 0.f;
    {
        const float* sY = sm + OFF_Y;
        const float* sW2 = sm + OFF_W2;
        #pragma unroll 8
        for (int kk = 0; kk < 128; ++kk) {
            float4 w = *(const float4*)(sW2 + kk * WPAD + (tx << 2));
            #pragma unroll
            for (int j = 0; j < 6; ++j) {
                float xv = sY[(m0 + j) * 128 + kk];
                acc[j][0] = fmaf(xv, w.x, acc[j][0]);
                acc[j][1] = fmaf(xv, w.y, acc[j][1]);
                acc[j][2] = fmaf(xv, w.z, acc[j][2]);
                acc[j][3] = fmaf(xv, w.w, acc[j][3]);
            }
        }
    }
    {
        float* sY2 = sm + OFF_Y2;
        float4 bv = ((const float4*)W2_b)[tx];
        #pragma unroll
        for (int j = 0; j < 6; ++j) {
            float4 r;
            r.x = gelu_erf(acc[j][0] + bv.x);
            r.y = gelu_erf(acc[j][1] + bv.y);
            r.z = gelu_erf(acc[j][2] + bv.z);
            r.w = gelu_erf(acc[j][3] + bv.w);
            ((float4*)(sY2 + (m0 + j) * 128))[tx] = r;
        }
    }
    __syncthreads();

    // stage W3 transposed (overwrites W2 region)
    {
        float* sW3 = sm + OFF_W3;
        const float4* W3f4 = (const float4*)W3_w;
        #pragma unroll
        for (int it = 0; it < 16; ++it) {
            int idx = it * NTHREADS + tid;
            int n = idx >> 5, q = idx & 31;
            float4 w = W3f4[n * 32 + q];
            int kk = q * 4;
            sW3[(kk + 0) * WPAD + n] = w.x;
            sW3[(kk + 1) * WPAD + n] = w.y;
            sW3[(kk + 2) * WPAD + n] = w.z;
            sW3[(kk + 3) * WPAD + n] = w.w;
        }
    }
    __syncthreads();

    // ---------------- Phase D: msg = Y2 @ W3^T + b3 ; masked sum over edges ----------------
    #pragma unroll
    for (int j = 0; j < 6; ++j)
        #pragma unroll
        for (int c = 0; c < 4; ++c) acc[j][c] = 0.f;
    {
        const float* sY2 = sm + OFF_Y2;
        const float* sW3 = sm + OFF_W3;
        #pragma unroll 8
        for (int kk = 0; kk < 128; ++kk) {
            float4 w = *(const float4*)(sW3 + kk * WPAD + (tx << 2));
            #pragma unroll
            for (int j = 0; j < 6; ++j) {
                float xv = sY2[(m0 + j) * 128 + kk];
                acc[j][0] = fmaf(xv, w.x, acc[j][0]);
                acc[j][1] = fmaf(xv, w.y, acc[j][1]);
                acc[j][2] = fmaf(xv, w.z, acc[j][2]);
                acc[j][3] = fmaf(xv, w.w, acc[j][3]);
            }
        }
    }
    {
        float* sRed = sm + OFF_RED;
        float4 bv = ((const float4*)W3_b)[tx];
        float p0 = 0.f, p1 = 0.f, p2 = 0.f, p3 = 0.f;
        #pragma unroll
        for (int j = 0; j < 6; ++j) {
            float ma = mask_attend[(size_t)ng * KNB + m0 + j];
            p0 = fmaf(ma, acc[j][0] + bv.x, p0);
            p1 = fmaf(ma, acc[j][1] + bv.y, p1);
            p2 = fmaf(ma, acc[j][2] + bv.z, p2);
            p3 = fmaf(ma, acc[j][3] + bv.w, p3);
        }
        float4 pv; pv.x = p0; pv.y = p1; pv.z = p2; pv.w = p3;
        ((float4*)(sRed + ty * 128))[tx] = pv;
    }
    __syncthreads();

    float* sVecA  = sm + OFF_VECA;
    float* sH     = sm + OFF_H;
    float* sF     = sm + OFF_F;
    float* sOPart = sm + OFF_OPART;
    float* sStats = sm + OFF_STATS;

    // dh = sum/30 ; pre-LN1 value x = h_V + dh
    if (tid < 128) {
        const float* sRed = sm + OFF_RED;
        float dh = 0.f;
        #pragma unroll
        for (int g = 0; g < 8; ++g) dh += sRed[g * 128 + tid];
        dh *= (1.0f / 30.0f);
        sVecA[tid] = h_V[(size_t)ng * Hdim + tid] + dh;
    }
    __syncthreads();
    ln_stats(sVecA, sStats, 0, tid);
    __syncthreads();
    if (tid < 128) {
        float hh = (sVecA[tid] - sStats[0]) * sStats[1] * ln1_g[tid] + ln1_b[tid];
        sH[tid] = hh;
    }
    __syncthreads();

    // ---------------- Phase E: FFN ----------------
    #pragma unroll
    for (int r = 0; r < 2; ++r) {
        int f = tid + r * NTHREADS;          // 0..511
        float a = Win_b[f];
        const float4* wrow = (const float4*)(Win_w + (size_t)f * 128);
        #pragma unroll
        for (int q = 0; q < 32; ++q) {
            float4 w = wrow[q];
            a = fmaf(w.x, sH[q * 4 + 0], a);
            a = fmaf(w.y, sH[q * 4 + 1], a);
            a = fmaf(w.z, sH[q * 4 + 2], a);
            a = fmaf(w.w, sH[q * 4 + 3], a);
        }
        sF[f] = gelu_erf(a);
    }
    __syncthreads();

    {
        int n = tid & 127, half = tid >> 7;
        const float4* wrow = (const float4*)(Wout_w + (size_t)n * FFdim + half * 256);
        const float* sFh = sF + half * 256;
        float a = 0.f;
        #pragma unroll
        for (int q = 0; q < 64; ++q) {
            float4 w = wrow[q];
            a = fmaf(w.x, sFh[q * 4 + 0], a);
            a = fmaf(w.y, sFh[q * 4 + 1], a);
            a = fmaf(w.z, sFh[q * 4 + 2], a);
            a = fmaf(w.w, sFh[q * 4 + 3], a);
        }
        sOPart[half * 128 + n] = a;
    }
    __syncthreads();

    if (tid < 128) {
        float dh2 = sOPart[tid] + sOPart[128 + tid] + Wout_b[tid];
        sVecA[tid] = sH[tid] + dh2;
    }
    __syncthreads();
    ln_stats(sVecA, sStats, 2, tid);
    __syncthreads();
    if (tid < 128) {
        float v = (sVecA[tid] - sStats[2]) * sStats[3] * ln2_g[tid] + ln2_b[tid];
        out[(size_t)ng * Hdim + tid] = mask_V[ng] * v;
    }
}

extern "C" void kernel_launch(void* const* d_in, const int* in_sizes, int n_in,
                              void* d_out, int out_size) {
    const float* h_V         = (const float*)d_in[0];
    const float* h_E         = (const float*)d_in[1];
    const float* mask_V      = (const float*)d_in[2];
    const float* mask_attend = (const float*)d_in[3];
    const float* W1_w        = (const float*)d_in[4];
    const float* W1_b        = (const float*)d_in[5];
    const float* W2_w        = (const float*)d_in[6];
    const float* W2_b        = (const float*)d_in[7];
    const float* W3_w        = (const float*)d_in[8];
    const float* W3_b        = (const float*)d_in[9];
    const float* ln1_g       = (const float*)d_in[10];
    const float* ln1_b       = (const float*)d_in[11];
    const float* ln2_g       = (const float*)d_in[12];
    const float* ln2_b       = (const float*)d_in[13];
    const float* Win_w       = (const float*)d_in[14];
    const float* Win_b       = (const float*)d_in[15];
    const float* Wout_w      = (const float*)d_in[16];
    const float* Wout_b      = (const float*)d_in[17];

    int nodes = in_sizes[0] / Hdim;   // B*N = 4096

    cudaFuncSetAttribute(decoder_layer_kernel,
                         cudaFuncAttributeMaxDynamicSharedMemorySize, SMEM_BYTES);

    decoder_layer_kernel<<<nodes, NTHREADS, SMEM_BYTES>>>(
        h_V, h_E, mask_V, mask_attend,
        W1_w, W1_b, W2_w, W2_b, W3_w, W3_b,
        ln1_g, ln1_b, ln2_g, ln2_b,
        Win_w, Win_b, Wout_w, Wout_b,
        (float*)d_out);
}

// round 4
// speedup vs baseline: 1.0187x; 1.0184x over previous
#include <cuda_runtime.h>
#include <math.h>

#define Hdim   128
#define NINdim 384
#define CIN    512
#define KNB    48
#define FFdim  512
#define NT     256

typedef unsigned long long u64;

// ---------------- pre-transposed weights (prep kernel output) ----------------
__device__ float g_W1t[512 * 128];    // W1t[k][n] = W1_w[n][k]
__device__ float g_W2t[128 * 128];    // W2t[k][n] = W2_w[n][k]
__device__ float g_W3td[128 * 256];   // W3td[k][2n+p] = W3_w[n][k]  (dup'd)

__global__ void prep_weights(const float* __restrict__ W1_w,
                             const float* __restrict__ W2_w,
                             const float* __restrict__ W3_w) {
    int idx = blockIdx.x * blockDim.x + threadIdx.x;
    if (idx < 65536) {                       // W1t
        int k = idx >> 7, n = idx & 127;
        g_W1t[idx] = W1_w[n * 512 + k];
    } else if (idx < 81920) {                // W2t
        int i = idx - 65536;
        int k = i >> 7, n = i & 127;
        g_W2t[i] = W2_w[n * 128 + k];
    } else if (idx < 114688) {               // W3td (duplicated along n)
        int i = idx - 81920;
        int k = i >> 8, r = i & 255, n = r >> 1;
        g_W3td[i] = W3_w[n * 128 + k];
    }
}

// ---------------- shared memory layout (floats) ----------------
// OFF_XD : Xdup[48][68]   (dup'd X k-tile, 32 k per tile)        3264
// OFF_W  : Wtile[4096]    (weight k-tile, all phases)            4096
// OFF_Y1 : Y1dup[48][260] (dup'd, pairs along n)                12480
// OFF_Y2 : Y2p[24][260]   (pair-interleaved along m)             6240
// tail (overlaps OFF_XD after phase B): sRed/sVec/sH/sF/sOP/sStats
#define OFF_XD 0
#define OFF_W  3264
#define OFF_Y1 7360
#define OFF_Y2 19840
#define SMEM_FLOATS 26080
#define SMEM_BYTES  (SMEM_FLOATS * 4)

#define T_RED 0
#define T_VEC 1024
#define T_H   1152
#define T_F   1280
#define T_OP  1792
#define T_ST  2048

__device__ __forceinline__ float gelu_erf(float x) {
    return 0.5f * x * (1.0f + erff(x * 0.70710678118654752440f));
}

__device__ __forceinline__ void fma2(u64& d, u64 a, u64 b) {
    asm("fma.rn.f32x2 %0, %1, %2, %0;" : "+l"(d) : "l"(a), "l"(b));
}
__device__ __forceinline__ void lds2(u64& a, u64& b, unsigned addr) {
    asm volatile("ld.shared.v2.b64 {%0,%1}, [%2];" : "=l"(a), "=l"(b) : "r"(addr));
}
__device__ __forceinline__ float2 unpk(u64 p) {
    float2 r;
    asm("mov.b64 {%0,%1}, %2;" : "=f"(r.x), "=f"(r.y) : "l"(p));
    return r;
}

__device__ __forceinline__ void ln_stats(const float* v, float* sStats, int o, int tid) {
    if (tid < 32) {
        float s = 0.f, s2 = 0.f;
        #pragma unroll
        for (int i = 0; i < 4; ++i) {
            float x = v[tid + i * 32];
            s += x; s2 += x * x;
        }
        #pragma unroll
        for (int off = 16; off > 0; off >>= 1) {
            s  += __shfl_xor_sync(0xffffffffu, s,  off);
            s2 += __shfl_xor_sync(0xffffffffu, s2, off);
        }
        if (tid == 0) {
            float mean = s * (1.0f / 128.0f);
            float var  = s2 * (1.0f / 128.0f) - mean * mean;
            sStats[o]     = mean;
            sStats[o + 1] = rsqrtf(var + 1e-5f);
        }
    }
}

__global__ void __launch_bounds__(NT, 2)
decoder_layer_kernel(
    const float* __restrict__ h_V, const float* __restrict__ h_E,
    const float* __restrict__ mask_V, const float* __restrict__ mask_attend,
    const float* __restrict__ W1_b, const float* __restrict__ W2_b,
    const float* __restrict__ W3_b,
    const float* __restrict__ ln1_g, const float* __restrict__ ln1_b,
    const float* __restrict__ ln2_g, const float* __restrict__ ln2_b,
    const float* __restrict__ Win_w, const float* __restrict__ Win_b,
    const float* __restrict__ Wout_w, const float* __restrict__ Wout_b,
    float* __restrict__ out)
{
    extern __shared__ float sm[];
    const int tid = threadIdx.x;
    const int tx  = tid & 31;      // covers n: cols 4tx..4tx+3
    const int ty  = tid >> 5;      // 0..7
    const int m0  = ty * 6;        // rows m0..m0+5 (even)
    const int ng  = blockIdx.x;

    const unsigned sbase = (unsigned)__cvta_generic_to_shared(sm);
    float* sXd = sm + OFF_XD;
    float* sW  = sm + OFF_W;
    float* sY1 = sm + OFF_Y1;
    float* sY2 = sm + OFF_Y2;

    u64 acc[12];

    // ================= Phase B: Y1 = gelu(X @ W1^T + b1), k-tiled =================
    #pragma unroll
    for (int i = 0; i < 12; ++i) acc[i] = 0ULL;

    {
        const float4* hv4 = (const float4*)(h_V + (size_t)ng * Hdim);
        const float4* he4 = (const float4*)(h_E + (size_t)ng * (KNB * NINdim));
        const unsigned xb = sbase + (OFF_XD + m0 * 68) * 4;
        const unsigned wb = sbase + OFF_W * 4 + tx * 16;

        for (int t = 0; t < 16; ++t) {
            const int k0 = t * 32;
            // stage X tile (dup'd): 48 rows x 8 float4
            #pragma unroll
            for (int i = 0; i < 2; ++i) {
                int id = i * NT + tid;
                if (id < 384) {
                    int m = id >> 3, q = id & 7;
                    float4 v = (k0 < 128) ? hv4[(k0 >> 2) + q]
                                          : he4[m * 96 + ((k0 - 128) >> 2) + q];
                    float* dst = sXd + m * 68 + 8 * q;
                    *(float4*)(dst)     = make_float4(v.x, v.x, v.y, v.y);
                    *(float4*)(dst + 4) = make_float4(v.z, v.z, v.w, v.w);
                }
            }
            // stage W1 tile: 4096 floats contiguous
            {
                const float4* src4 = (const float4*)(g_W1t + k0 * 128);
                float4* dst4 = (float4*)sW;
                #pragma unroll
                for (int i = 0; i < 4; ++i) dst4[i * NT + tid] = src4[i * NT + tid];
            }
            __syncthreads();

            #pragma unroll 4
            for (int kk = 0; kk < 32; kk += 2) {
                u64 wa0, wa1, wb0, wb1;
                lds2(wa0, wa1, wb + kk * 512);
                lds2(wb0, wb1, wb + kk * 512 + 512);
                #pragma unroll
                for (int j = 0; j < 6; ++j) {
                    u64 x0, x1;
                    lds2(x0, x1, xb + j * 272 + kk * 8);
                    fma2(acc[j * 2 + 0], x0, wa0);
                    fma2(acc[j * 2 + 1], x0, wa1);
                    fma2(acc[j * 2 + 0], x1, wb0);
                    fma2(acc[j * 2 + 1], x1, wb1);
                }
            }
            __syncthreads();
        }
    }
    // epilogue B -> Y1dup
    {
        float4 bv = ((const float4*)W1_b)[tx];
        #pragma unroll
        for (int j = 0; j < 6; ++j) {
            float2 p0 = unpk(acc[j * 2 + 0]);
            float2 p1 = unpk(acc[j * 2 + 1]);
            float y0 = gelu_erf(p0.x + bv.x), y1 = gelu_erf(p0.y + bv.y);
            float y2 = gelu_erf(p1.x + bv.z), y3 = gelu_erf(p1.y + bv.w);
            float* dst = sY1 + (m0 + j) * 260 + 8 * tx;
            *(float4*)(dst)     = make_float4(y0, y0, y1, y1);
            *(float4*)(dst + 4) = make_float4(y2, y2, y3, y3);
        }
    }

    // ================= Phase C: Y2 = gelu(Y1 @ W2^T + b2) =================
    #pragma unroll
    for (int i = 0; i < 12; ++i) acc[i] = 0ULL;
    {
        const unsigned xb = sbase + (OFF_Y1 + m0 * 260) * 4;
        const unsigned wb = sbase + OFF_W * 4 + tx * 16;
        for (int kt = 0; kt < 4; ++kt) {
            {
                const float4* src4 = (const float4*)(g_W2t + kt * 4096);
                float4* dst4 = (float4*)sW;
                #pragma unroll
                for (int i = 0; i < 4; ++i) dst4[i * NT + tid] = src4[i * NT + tid];
            }
            __syncthreads();
            const unsigned xoff = xb + kt * 256;
            #pragma unroll 4
            for (int kk = 0; kk < 32; kk += 2) {
                u64 wa0, wa1, wb0, wb1;
                lds2(wa0, wa1, wb + kk * 512);
                lds2(wb0, wb1, wb + kk * 512 + 512);
                #pragma unroll
                for (int j = 0; j < 6; ++j) {
                    u64 x0, x1;
                    lds2(x0, x1, xoff + j * 1040 + kk * 8);
                    fma2(acc[j * 2 + 0], x0, wa0);
                    fma2(acc[j * 2 + 1], x0, wa1);
                    fma2(acc[j * 2 + 0], x1, wb0);
                    fma2(acc[j * 2 + 1], x1, wb1);
                }
            }
            __syncthreads();
        }
    }
    // epilogue C -> Y2 pair-interleaved (pairs along m)
    {
        float4 bv = ((const float4*)W2_b)[tx];
        #pragma unroll
        for (int a = 0; a < 3; ++a) {
            float2 A0 = unpk(acc[(2 * a) * 2 + 0]);
            float2 A1 = unpk(acc[(2 * a) * 2 + 1]);
            float2 B0 = unpk(acc[(2 * a + 1) * 2 + 0]);
            float2 B1 = unpk(acc[(2 * a + 1) * 2 + 1]);
            float y00 = gelu_erf(A0.x + bv.x), y01 = gelu_erf(A0.y + bv.y);
            float y02 = gelu_erf(A1.x + bv.z), y03 = gelu_erf(A1.y + bv.w);
            float y10 = gelu_erf(B0.x + bv.x), y11 = gelu_erf(B0.y + bv.y);
            float y12 = gelu_erf(B1.x + bv.z), y13 = gelu_erf(B1.y + bv.w);
            float* dst = sY2 + (3 * ty + a) * 260 + 8 * tx;
            *(float2*)(dst + 0) = make_float2(y00, y10);
            *(float2*)(dst + 2) = make_float2(y01, y11);
            *(float2*)(dst + 4) = make_float2(y02, y12);
            *(float2*)(dst + 6) = make_float2(y03, y13);
        }
    }

    // ================= Phase D: msg = Y2 @ W3^T + b3, masked sum =================
    #pragma unroll
    for (int i = 0; i < 12; ++i) acc[i] = 0ULL;
    {
        const unsigned xb = sbase + (OFF_Y2 + (3 * ty) * 260) * 4;
        const unsigned wb = sbase + OFF_W * 4 + tx * 32;
        for (int kt = 0; kt < 8; ++kt) {
            {
                const float4* src4 = (const float4*)(g_W3td + kt * 4096);
                float4* dst4 = (float4*)sW;
                #pragma unroll
                for (int i = 0; i < 4; ++i) dst4[i * NT + tid] = src4[i * NT + tid];
            }
            __syncthreads();
            const unsigned xoff = xb + kt * 128;   // 16 k per tile, 8 bytes per k
            #pragma unroll 2
            for (int kk = 0; kk < 16; kk += 2) {
                u64 w00, w11, w22, w33, v00, v11, v22, v33;
                lds2(w00, w11, wb + kk * 1024);
                lds2(w22, w33, wb + kk * 1024 + 16);
                lds2(v00, v11, wb + kk * 1024 + 1024);
                lds2(v22, v33, wb + kk * 1024 + 1040);
                #pragma unroll
                for (int a = 0; a < 3; ++a) {
                    u64 x0, x1;
                    lds2(x0, x1, xoff + a * 1040 + kk * 8);
                    fma2(acc[a * 4 + 0], x0, w00);
                    fma2(acc[a * 4 + 1], x0, w11);
                    fma2(acc[a * 4 + 2], x0, w22);
                    fma2(acc[a * 4 + 3], x0, w33);
                    fma2(acc[a * 4 + 0], x1, v00);
                    fma2(acc[a * 4 + 1], x1, v11);
                    fma2(acc[a * 4 + 2], x1, v22);
                    fma2(acc[a * 4 + 3], x1, v33);
                }
            }
            __syncthreads();
        }
    }
    // epilogue D: bias + mask + per-warp partial sums
    float* sRed = sm + T_RED;
    {
        float4 bv = ((const float4*)W3_b)[tx];
        float p0 = 0.f, p1 = 0.f, p2 = 0.f, p3 = 0.f;
        #pragma unroll
        for (int a = 0; a < 3; ++a) {
            float mA = mask_attend[(size_t)ng * KNB + m0 + 2 * a];
            float mB = mask_attend[(size_t)ng * KNB + m0 + 2 * a + 1];
            float2 c0 = unpk(acc[a * 4 + 0]);
            float2 c1 = unpk(acc[a * 4 + 1]);
            float2 c2 = unpk(acc[a * 4 + 2]);
            float2 c3 = unpk(acc[a * 4 + 3]);
            p0 += mA * (c0.x + bv.x) + mB * (c0.y + bv.x);
            p1 += mA * (c1.x + bv.y) + mB * (c1.y + bv.y);
            p2 += mA * (c2.x + bv.z) + mB * (c2.y + bv.z);
            p3 += mA * (c3.x + bv.w) + mB * (c3.y + bv.w);
        }
        ((float4*)(sRed + ty * 128))[tx] = make_float4(p0, p1, p2, p3);
    }
    __syncthreads();

    float* sVec   = sm + T_VEC;
    float* sH     = sm + T_H;
    float* sF     = sm + T_F;
    float* sOP    = sm + T_OP;
    float* sStats = sm + T_ST;

    if (tid < 128) {
        float dh = 0.f;
        #pragma unroll
        for (int g = 0; g < 8; ++g) dh += sRed[g * 128 + tid];
        dh *= (1.0f / 30.0f);
        sVec[tid] = h_V[(size_t)ng * Hdim + tid] + dh;
    }
    __syncthreads();
    ln_stats(sVec, sStats, 0, tid);
    __syncthreads();
    if (tid < 128) {
        sH[tid] = (sVec[tid] - sStats[0]) * sStats[1] * ln1_g[tid] + ln1_b[tid];
    }
    __syncthreads();

    // ================= FFN =================
    #pragma unroll
    for (int r = 0; r < 2; ++r) {
        int f = tid + r * NT;
        float a = Win_b[f];
        const float4* wrow = (const float4*)(Win_w + (size_t)f * 128);
        #pragma unroll
        for (int q = 0; q < 32; ++q) {
            float4 w = wrow[q];
            a = fmaf(w.x, sH[q * 4 + 0], a);
            a = fmaf(w.y, sH[q * 4 + 1], a);
            a = fmaf(w.z, sH[q * 4 + 2], a);
            a = fmaf(w.w, sH[q * 4 + 3], a);
        }
        sF[f] = gelu_erf(a);
    }
    __syncthreads();

    {
        int n = tid & 127, half = tid >> 7;
        const float4* wrow = (const float4*)(Wout_w + (size_t)n * FFdim + half * 256);
        const float* sFh = sF + half * 256;
        float a = 0.f;
        #pragma unroll
        for (int q = 0; q < 64; ++q) {
            float4 w = wrow[q];
            a = fmaf(w.x, sFh[q * 4 + 0], a);
            a = fmaf(w.y, sFh[q * 4 + 1], a);
            a = fmaf(w.z, sFh[q * 4 + 2], a);
            a = fmaf(w.w, sFh[q * 4 + 3], a);
        }
        sOP[half * 128 + n] = a;
    }
    __syncthreads();

    if (tid < 128) {
        float dh2 = sOP[tid] + sOP[128 + tid] + Wout_b[tid];
        sVec[tid] = sH[tid] + dh2;
    }
    __syncthreads();
    ln_stats(sVec, sStats, 2, tid);
    __syncthreads();
    if (tid < 128) {
        float v = (sVec[tid] - sStats[2]) * sStats[3] * ln2_g[tid] + ln2_b[tid];
        out[(size_t)ng * Hdim + tid] = mask_V[ng] * v;
    }
}

extern "C" void kernel_launch(void* const* d_in, const int* in_sizes, int n_in,
                              void* d_out, int out_size) {
    const float* h_V         = (const float*)d_in[0];
    const float* h_E         = (const float*)d_in[1];
    const float* mask_V      = (const float*)d_in[2];
    const float* mask_attend = (const float*)d_in[3];
    const float* W1_w        = (const float*)d_in[4];
    const float* W1_b        = (const float*)d_in[5];
    const float* W2_w        = (const float*)d_in[6];
    const float* W2_b        = (const float*)d_in[7];
    const float* W3_w        = (const float*)d_in[8];
    const float* W3_b        = (const float*)d_in[9];
    const float* ln1_g       = (const float*)d_in[10];
    const float* ln1_b       = (const float*)d_in[11];
    const float* ln2_g       = (const float*)d_in[12];
    const float* ln2_b       = (const float*)d_in[13];
    const float* Win_w       = (const float*)d_in[14];
    const float* Win_b       = (const float*)d_in[15];
    const float* Wout_w      = (const float*)d_in[16];
    const float* Wout_b      = (const float*)d_in[17];

    int nodes = in_sizes[0] / Hdim;

    prep_weights<<<448, 256>>>(W1_w, W2_w, W3_w);

    cudaFuncSetAttribute(decoder_layer_kernel,
                         cudaFuncAttributeMaxDynamicSharedMemorySize, SMEM_BYTES);

    decoder_layer_kernel<<<nodes, NT, SMEM_BYTES>>>(
        h_V, h_E, mask_V, mask_attend,
        W1_b, W2_b, W3_b,
        ln1_g, ln1_b, ln2_g, ln2_b,
        Win_w, Win_b, Wout_w, Wout_b,
        (float*)d_out);
}

// round 5
// speedup vs baseline: 1.4617x; 1.4349x over previous
#include <cuda_runtime.h>
#include <math.h>

#define Hdim   128
#define NINdim 384
#define CIN    512
#define KNB    48
#define FFdim  512
#define NT     256

typedef unsigned long long u64;

// ---------------- pre-paired weights (prep kernel output) ----------------
// Wp[k2][n] = (W[n][2k2], W[n][2k2+1])  -- k-pair interleaved, n contiguous
__device__ float2 g_W1p[256 * 128];
__device__ float2 g_W2p[64 * 128];
__device__ float2 g_W3p[64 * 128];
__device__ float2 g_Winp[64 * 512];    // [k2][f]
__device__ float2 g_Woutp[256 * 128];  // [k2][n]
__device__ float  g_Hbuf[4096 * 128];  // post-LN1 hidden

__global__ void prep_weights(const float* __restrict__ W1_w,
                             const float* __restrict__ W2_w,
                             const float* __restrict__ W3_w,
                             const float* __restrict__ Win_w,
                             const float* __restrict__ Wout_w) {
    int idx = blockIdx.x * blockDim.x + threadIdx.x;
    if (idx < 32768) {                         // W1p: k2<256, n<128
        int k2 = idx >> 7, n = idx & 127;
        g_W1p[idx] = make_float2(W1_w[n * 512 + 2 * k2], W1_w[n * 512 + 2 * k2 + 1]);
    } else if (idx < 40960) {                  // W2p: k2<64
        int i = idx - 32768;
        int k2 = i >> 7, n = i & 127;
        g_W2p[i] = make_float2(W2_w[n * 128 + 2 * k2], W2_w[n * 128 + 2 * k2 + 1]);
    } else if (idx < 49152) {                  // W3p
        int i = idx - 40960;
        int k2 = i >> 7, n = i & 127;
        g_W3p[i] = make_float2(W3_w[n * 128 + 2 * k2], W3_w[n * 128 + 2 * k2 + 1]);
    } else if (idx < 81920) {                  // Winp: k2<64, f<512
        int i = idx - 49152;
        int k2 = i >> 9, f = i & 511;
        g_Winp[i] = make_float2(Win_w[f * 128 + 2 * k2], Win_w[f * 128 + 2 * k2 + 1]);
    } else if (idx < 114688) {                 // Woutp: k2<256, n<128
        int i = idx - 81920;
        int k2 = i >> 7, n = i & 127;
        g_Woutp[i] = make_float2(Wout_w[n * 512 + 2 * k2], Wout_w[n * 512 + 2 * k2 + 1]);
    }
}

// ---------------- kernel-1 shared layout (floats) ----------------
#define OFF_X   0        // X [48][512]           24576
#define OFF_W   24576    // weight tile           16384 (64KB = 8192 float2)
#define OFF_Y1  40960    // Y1 [48][128]           6144
#define OFF_Y2  47104    // Y2 [48][128]           6144
#define OFF_RED 53248    // [8][128]               1024
#define OFF_VEC 54272    // [128]
#define OFF_ST  54400    // [8]
#define SM1_FLOATS 54408
#define SM1_BYTES  (SM1_FLOATS * 4)

// ---------------- kernel-2 shared layout ----------------
#define K2_H   0         // H [32][128]            4096
#define K2_W   4096      // weight tile           16384
#define K2_F   20480     // F [32][512]           16384
#define SM2_FLOATS 36864
#define SM2_BYTES  (SM2_FLOATS * 4)

__device__ __forceinline__ float gelu_erf(float x) {
    return 0.5f * x * (1.0f + erff(x * 0.70710678118654752440f));
}
__device__ __forceinline__ void fma2(u64& d, u64 a, u64 b) {
    asm("fma.rn.f32x2 %0, %1, %2, %0;" : "+l"(d) : "l"(a), "l"(b));
}
__device__ __forceinline__ void lds2(u64& a, u64& b, unsigned addr) {
    asm volatile("ld.shared.v2.b64 {%0,%1}, [%2];" : "=l"(a), "=l"(b) : "r"(addr));
}
__device__ __forceinline__ float hadd(u64 p) {
    float lo, hi;
    asm("mov.b64 {%0,%1}, %2;" : "=f"(lo), "=f"(hi) : "l"(p));
    return lo + hi;
}

__device__ __forceinline__ void ln_stats(const float* v, float* sStats, int o, int tid) {
    if (tid < 32) {
        float s = 0.f, s2 = 0.f;
        #pragma unroll
        for (int i = 0; i < 4; ++i) {
            float x = v[tid + i * 32];
            s += x; s2 += x * x;
        }
        #pragma unroll
        for (int off = 16; off > 0; off >>= 1) {
            s  += __shfl_xor_sync(0xffffffffu, s,  off);
            s2 += __shfl_xor_sync(0xffffffffu, s2, off);
        }
        if (tid == 0) {
            float mean = s * (1.0f / 128.0f);
            float var  = s2 * (1.0f / 128.0f) - mean * mean;
            sStats[o]     = mean;
            sStats[o + 1] = rsqrtf(var + 1e-5f);
        }
    }
}

// stage 16384 contiguous floats into sW
__device__ __forceinline__ void stage_w(float* sW, const float2* src, int tid) {
    const float4* s4 = (const float4*)src;
    float4* d4 = (float4*)sW;
    #pragma unroll
    for (int i = 0; i < 16; ++i) d4[i * NT + tid] = s4[i * NT + tid];
}

// one 2-k2 step (4 k): 6 m-rows, 4 n per lane
#define INNER6(XB, XSTRIDE, WB)                                        \
  {                                                                    \
    u64 w00, w01, w02, w03, w10, w11, w12, w13;                        \
    lds2(w00, w01, (WB));        lds2(w02, w03, (WB) + 16);            \
    lds2(w10, w11, (WB) + 1024); lds2(w12, w13, (WB) + 1040);          \
    _Pragma("unroll")                                                  \
    for (int j = 0; j < 6; ++j) {                                      \
      u64 xa, xb; lds2(xa, xb, (XB) + j * (XSTRIDE));                  \
      fma2(acc[j][0], xa, w00); fma2(acc[j][1], xa, w01);              \
      fma2(acc[j][2], xa, w02); fma2(acc[j][3], xa, w03);              \
      fma2(acc[j][0], xb, w10); fma2(acc[j][1], xb, w11);              \
      fma2(acc[j][2], xb, w12); fma2(acc[j][3], xb, w13);              \
    }                                                                  \
  }

#define INNER4(XB, XSTRIDE, WB)                                        \
  {                                                                    \
    u64 w00, w01, w02, w03, w10, w11, w12, w13;                        \
    lds2(w00, w01, (WB));        lds2(w02, w03, (WB) + 16);            \
    lds2(w10, w11, (WB) + 1024); lds2(w12, w13, (WB) + 1040);          \
    _Pragma("unroll")                                                  \
    for (int j = 0; j < 4; ++j) {                                      \
      u64 xa, xb; lds2(xa, xb, (XB) + j * (XSTRIDE));                  \
      fma2(acc[j][0], xa, w00); fma2(acc[j][1], xa, w01);              \
      fma2(acc[j][2], xa, w02); fma2(acc[j][3], xa, w03);              \
      fma2(acc[j][0], xb, w10); fma2(acc[j][1], xb, w11);              \
      fma2(acc[j][2], xb, w12); fma2(acc[j][3], xb, w13);              \
    }                                                                  \
  }

// =========================================================================
// Kernel 1: per node — edge MLP (3 layers), masked aggregate, LN1 -> g_Hbuf
// =========================================================================
__global__ void __launch_bounds__(NT, 1)
edge_mlp_kernel(
    const float* __restrict__ h_V, const float* __restrict__ h_E,
    const float* __restrict__ mask_attend,
    const float* __restrict__ W1_b, const float* __restrict__ W2_b,
    const float* __restrict__ W3_b,
    const float* __restrict__ ln1_g, const float* __restrict__ ln1_b)
{
    extern __shared__ float sm[];
    const int tid = threadIdx.x;
    const int tx  = tid & 31;      // lane: n = 4*tx .. 4*tx+3
    const int ty  = tid >> 5;      // warp: m = 6*ty .. 6*ty+5
    const int m0  = ty * 6;
    const int ng  = blockIdx.x;

    const unsigned sbase = (unsigned)__cvta_generic_to_shared(sm);
    float* sX  = sm + OFF_X;
    float* sW  = sm + OFF_W;
    float* sY1 = sm + OFF_Y1;
    float* sY2 = sm + OFF_Y2;

    // ---- stage X [48][512] ----
    {
        const float4* hv4 = (const float4*)(h_V + (size_t)ng * Hdim);
        #pragma unroll
        for (int it = 0; it < 6; ++it) {
            int idx = it * NT + tid;
            int m = idx >> 5, q = idx & 31;
            ((float4*)sX)[m * 128 + q] = hv4[q];
        }
        const float4* he4 = (const float4*)(h_E + (size_t)ng * (KNB * NINdim));
        #pragma unroll
        for (int it = 0; it < 18; ++it) {
            int idx = it * NT + tid;
            int m = idx / 96, q = idx - m * 96;
            ((float4*)sX)[m * 128 + 32 + q] = he4[idx];
        }
    }

    u64 acc[6][4];
    const unsigned wl = sbase + OFF_W * 4 + tx * 32;

    // ================= Phase B: Y1 = gelu(X @ W1^T + b1) =================
    #pragma unroll
    for (int j = 0; j < 6; ++j)
        #pragma unroll
        for (int c = 0; c < 4; ++c) acc[j][c] = 0ULL;
    {
        const unsigned xrow = sbase + OFF_X * 4 + m0 * 2048;
        for (int kt = 0; kt < 4; ++kt) {
            __syncthreads();
            stage_w(sW, g_W1p + kt * 8192, tid);
            __syncthreads();
            #pragma unroll 2
            for (int it = 0; it < 32; ++it)
                INNER6(xrow + kt * 512 + it * 16, 2048, wl + it * 2048);
        }
    }
    {
        float4 bv = ((const float4*)W1_b)[tx];
        #pragma unroll
        for (int j = 0; j < 6; ++j) {
            float4 r;
            r.x = gelu_erf(hadd(acc[j][0]) + bv.x);
            r.y = gelu_erf(hadd(acc[j][1]) + bv.y);
            r.z = gelu_erf(hadd(acc[j][2]) + bv.z);
            r.w = gelu_erf(hadd(acc[j][3]) + bv.w);
            *(float4*)(sY1 + (m0 + j) * 128 + 4 * tx) = r;
            acc[j][0] = acc[j][1] = acc[j][2] = acc[j][3] = 0ULL;
        }
    }
    __syncthreads();

    // ================= Phase C: Y2 = gelu(Y1 @ W2^T + b2) =================
    stage_w(sW, g_W2p, tid);
    __syncthreads();
    {
        const unsigned xrow = sbase + OFF_Y1 * 4 + m0 * 512;
        #pragma unroll 2
        for (int it = 0; it < 32; ++it)
            INNER6(xrow + it * 16, 512, wl + it * 2048);
    }
    {
        float4 bv = ((const float4*)W2_b)[tx];
        #pragma unroll
        for (int j = 0; j < 6; ++j) {
            float4 r;
            r.x = gelu_erf(hadd(acc[j][0]) + bv.x);
            r.y = gelu_erf(hadd(acc[j][1]) + bv.y);
            r.z = gelu_erf(hadd(acc[j][2]) + bv.z);
            r.w = gelu_erf(hadd(acc[j][3]) + bv.w);
            *(float4*)(sY2 + (m0 + j) * 128 + 4 * tx) = r;
            acc[j][0] = acc[j][1] = acc[j][2] = acc[j][3] = 0ULL;
        }
    }
    __syncthreads();

    // ================= Phase D: msg = Y2 @ W3^T + b3, masked sum =================
    stage_w(sW, g_W3p, tid);
    __syncthreads();
    {
        const unsigned xrow = sbase + OFF_Y2 * 4 + m0 * 512;
        #pragma unroll 2
        for (int it = 0; it < 32; ++it)
            INNER6(xrow + it * 16, 512, wl + it * 2048);
    }
    float* sRed = sm + OFF_RED;
    {
        float4 bv = ((const float4*)W3_b)[tx];
        float p0 = 0.f, p1 = 0.f, p2 = 0.f, p3 = 0.f;
        #pragma unroll
        for (int j = 0; j < 6; ++j) {
            float ma = mask_attend[(size_t)ng * KNB + m0 + j];
            p0 = fmaf(ma, hadd(acc[j][0]) + bv.x, p0);
            p1 = fmaf(ma, hadd(acc[j][1]) + bv.y, p1);
            p2 = fmaf(ma, hadd(acc[j][2]) + bv.z, p2);
            p3 = fmaf(ma, hadd(acc[j][3]) + bv.w, p3);
        }
        *(float4*)(sRed + ty * 128 + 4 * tx) = make_float4(p0, p1, p2, p3);
    }
    __syncthreads();

    float* sVec   = sm + OFF_VEC;
    float* sStats = sm + OFF_ST;
    if (tid < 128) {
        float dh = 0.f;
        #pragma unroll
        for (int g = 0; g < 8; ++g) dh += sRed[g * 128 + tid];
        dh *= (1.0f / 30.0f);
        sVec[tid] = h_V[(size_t)ng * Hdim + tid] + dh;
    }
    __syncthreads();
    ln_stats(sVec, sStats, 0, tid);
    __syncthreads();
    if (tid < 128) {
        g_Hbuf[(size_t)ng * Hdim + tid] =
            (sVec[tid] - sStats[0]) * sStats[1] * ln1_g[tid] + ln1_b[tid];
    }
}

// =========================================================================
// Kernel 2: batched FFN + LN2 + mask (32 nodes per CTA)
// =========================================================================
__global__ void __launch_bounds__(NT, 1)
ffn_kernel(const float* __restrict__ mask_V,
           const float* __restrict__ Win_b, const float* __restrict__ Wout_b,
           const float* __restrict__ ln2_g, const float* __restrict__ ln2_b,
           float* __restrict__ out)
{
    extern __shared__ float sm[];
    const int tid = threadIdx.x;
    const int tx  = tid & 31;
    const int ty  = tid >> 5;
    const int m0  = ty * 4;             // 4 nodes per warp
    const int nb  = blockIdx.x * 32;    // node base

    const unsigned sbase = (unsigned)__cvta_generic_to_shared(sm);
    float* sH = sm + K2_H;
    float* sW = sm + K2_W;
    float* sF = sm + K2_F;
    const unsigned wl = sbase + K2_W * 4 + tx * 32;

    // stage H [32][128]
    {
        const float4* src = (const float4*)(g_Hbuf + (size_t)nb * Hdim);
        float4* dst = (float4*)sH;
        #pragma unroll
        for (int i = 0; i < 4; ++i) dst[i * NT + tid] = src[i * NT + tid];
    }

    u64 acc[4][4];

    // ---- GEMM1: F = gelu(H @ Win^T + bin), n-blocked over 512 ----
    for (int nblk = 0; nblk < 4; ++nblk) {
        __syncthreads();
        // stage Win column block [64 k2][128 f]
        {
            const float4* s4 = (const float4*)g_Winp;
            float4* d4 = (float4*)sW;
            #pragma unroll
            for (int i = 0; i < 16; ++i) {
                int id4 = i * NT + tid;             // 0..4095
                int k2 = id4 >> 6, c4 = id4 & 63;
                d4[id4] = s4[k2 * 256 + nblk * 64 + c4];
            }
        }
        __syncthreads();
        #pragma unroll
        for (int j = 0; j < 4; ++j)
            #pragma unroll
            for (int c = 0; c < 4; ++c) acc[j][c] = 0ULL;
        {
            const unsigned xrow = sbase + K2_H * 4 + m0 * 512;
            #pragma unroll 2
            for (int it = 0; it < 32; ++it)
                INNER4(xrow + it * 16, 512, wl + it * 2048);
        }
        float4 bv = ((const float4*)Win_b)[nblk * 32 + tx];
        #pragma unroll
        for (int j = 0; j < 4; ++j) {
            float4 r;
            r.x = gelu_erf(hadd(acc[j][0]) + bv.x);
            r.y = gelu_erf(hadd(acc[j][1]) + bv.y);
            r.z = gelu_erf(hadd(acc[j][2]) + bv.z);
            r.w = gelu_erf(hadd(acc[j][3]) + bv.w);
            *(float4*)(sF + (m0 + j) * 512 + nblk * 128 + 4 * tx) = r;
        }
    }

    // ---- GEMM2: O = F @ Wout^T ----
    #pragma unroll
    for (int j = 0; j < 4; ++j)
        #pragma unroll
        for (int c = 0; c < 4; ++c) acc[j][c] = 0ULL;
    for (int kt = 0; kt < 4; ++kt) {
        __syncthreads();
        stage_w(sW, g_Woutp + kt * 8192, tid);
        __syncthreads();
        const unsigned xrow = sbase + K2_F * 4 + m0 * 2048;
        #pragma unroll 2
        for (int it = 0; it < 32; ++it)
            INNER4(xrow + kt * 512 + it * 16, 2048, wl + it * 2048);
    }

    // ---- residual + LN2 + mask, per warp row (shfl) ----
    {
        float4 bv = ((const float4*)Wout_b)[tx];
        float4 gv = ((const float4*)ln2_g)[tx];
        float4 lb = ((const float4*)ln2_b)[tx];
        #pragma unroll
        for (int j = 0; j < 4; ++j) {
            const float* hrow = sH + (m0 + j) * 128 + 4 * tx;
            float v0 = hadd(acc[j][0]) + bv.x + hrow[0];
            float v1 = hadd(acc[j][1]) + bv.y + hrow[1];
            float v2 = hadd(acc[j][2]) + bv.z + hrow[2];
            float v3 = hadd(acc[j][3]) + bv.w + hrow[3];
            float s  = v0 + v1 + v2 + v3;
            float s2 = v0 * v0 + v1 * v1 + v2 * v2 + v3 * v3;
            #pragma unroll
            for (int off = 16; off > 0; off >>= 1) {
                s  += __shfl_xor_sync(0xffffffffu, s,  off);
                s2 += __shfl_xor_sync(0xffffffffu, s2, off);
            }
            float mean = s * (1.0f / 128.0f);
            float rstd = rsqrtf(s2 * (1.0f / 128.0f) - mean * mean + 1e-5f);
            float mv = mask_V[nb + m0 + j];
            float4 r;
            r.x = mv * ((v0 - mean) * rstd * gv.x + lb.x);
            r.y = mv * ((v1 - mean) * rstd * gv.y + lb.y);
            r.z = mv * ((v2 - mean) * rstd * gv.z + lb.z);
            r.w = mv * ((v3 - mean) * rstd * gv.w + lb.w);
            *(float4*)(out + (size_t)(nb + m0 + j) * Hdim + 4 * tx) = r;
        }
    }
}

extern "C" void kernel_launch(void* const* d_in, const int* in_sizes, int n_in,
                              void* d_out, int out_size) {
    const float* h_V         = (const float*)d_in[0];
    const float* h_E         = (const float*)d_in[1];
    const float* mask_V      = (const float*)d_in[2];
    const float* mask_attend = (const float*)d_in[3];
    const float* W1_w        = (const float*)d_in[4];
    const float* W1_b        = (const float*)d_in[5];
    const float* W2_w        = (const float*)d_in[6];
    const float* W2_b        = (const float*)d_in[7];
    const float* W3_w        = (const float*)d_in[8];
    const float* W3_b        = (const float*)d_in[9];
    const float* ln1_g       = (const float*)d_in[10];
    const float* ln1_b       = (const float*)d_in[11];
    const float* ln2_g       = (const float*)d_in[12];
    const float* ln2_b       = (const float*)d_in[13];
    const float* Win_w       = (const float*)d_in[14];
    const float* Win_b       = (const float*)d_in[15];
    const float* Wout_w      = (const float*)d_in[16];
    const float* Wout_b      = (const float*)d_in[17];

    int nodes = in_sizes[0] / Hdim;   // 4096

    prep_weights<<<448, 256>>>(W1_w, W2_w, W3_w, Win_w, Wout_w);

    cudaFuncSetAttribute(edge_mlp_kernel,
                         cudaFuncAttributeMaxDynamicSharedMemorySize, SM1_BYTES);
    cudaFuncSetAttribute(ffn_kernel,
                         cudaFuncAttributeMaxDynamicSharedMemorySize, SM2_BYTES);

    edge_mlp_kernel<<<nodes, NT, SM1_BYTES>>>(
        h_V, h_E, mask_attend, W1_b, W2_b, W3_b, ln1_g, ln1_b);

    ffn_kernel<<<nodes / 32, NT, SM2_BYTES>>>(
        mask_V, Win_b, Wout_b, ln2_g, ln2_b, (float*)d_out);
}

// round 6
// speedup vs baseline: 1.6656x; 1.1395x over previous
#include <cuda_runtime.h>
#include <math.h>

#define Hdim   128
#define NINdim 384
#define CIN    512
#define KNB    48
#define FFdim  512
#define NT     256

typedef unsigned long long u64;

// ---------------- pre-paired weights (prep kernel output) ----------------
// Wp[k2][n] = (W[n][2k2], W[n][2k2+1])  -- k-pair interleaved, n contiguous
__device__ float2 g_W1p[256 * 128];
__device__ float2 g_W2p[64 * 128];
__device__ float2 g_W3p[64 * 128];
__device__ float2 g_Winp[64 * 512];    // [k2][f]
__device__ float2 g_Woutp[256 * 128];  // [k2][n]
__device__ float  g_Hbuf[4096 * 128];  // post-LN1 hidden

__global__ void prep_weights(const float* __restrict__ W1_w,
                             const float* __restrict__ W2_w,
                             const float* __restrict__ W3_w,
                             const float* __restrict__ Win_w,
                             const float* __restrict__ Wout_w) {
    int idx = blockIdx.x * blockDim.x + threadIdx.x;
    if (idx < 32768) {                         // W1p: k2<256, n<128
        int k2 = idx >> 7, n = idx & 127;
        g_W1p[idx] = make_float2(W1_w[n * 512 + 2 * k2], W1_w[n * 512 + 2 * k2 + 1]);
    } else if (idx < 40960) {                  // W2p: k2<64
        int i = idx - 32768;
        int k2 = i >> 7, n = i & 127;
        g_W2p[i] = make_float2(W2_w[n * 128 + 2 * k2], W2_w[n * 128 + 2 * k2 + 1]);
    } else if (idx < 49152) {                  // W3p
        int i = idx - 40960;
        int k2 = i >> 7, n = i & 127;
        g_W3p[i] = make_float2(W3_w[n * 128 + 2 * k2], W3_w[n * 128 + 2 * k2 + 1]);
    } else if (idx < 81920) {                  // Winp: k2<64, f<512
        int i = idx - 49152;
        int k2 = i >> 9, f = i & 511;
        g_Winp[i] = make_float2(Win_w[f * 128 + 2 * k2], Win_w[f * 128 + 2 * k2 + 1]);
    } else if (idx < 114688) {                 // Woutp: k2<256, n<128
        int i = idx - 81920;
        int k2 = i >> 7, n = i & 127;
        g_Woutp[i] = make_float2(Wout_w[n * 512 + 2 * k2], Wout_w[n * 512 + 2 * k2 + 1]);
    }
}

// ---------------- kernel-1 shared layout (floats), 2 CTAs/SM ----------------
// OFF_A : X k-tile [48][128] during B; Y2 [48][128] during C-out/D   6144
// OFF_W : weight tile (64 k2 x 128 n float2)                        16384
// OFF_Y1: Y1 [48][128]; tail scratch (RED/VEC/ST) after phase D      6144
#define OFF_A   0
#define OFF_W   6144
#define OFF_Y1  22528
#define T_RED   22528
#define T_VEC   23552
#define T_ST    23680
#define SM1_FLOATS 28672
#define SM1_BYTES  (SM1_FLOATS * 4)     // 114688 B -> 2 CTAs/SM

// ---------------- kernel-2 shared layout ----------------
#define K2_H   0         // H [32][128]            4096
#define K2_W   4096      // weight tile           16384
#define K2_F   20480     // F [32][512]           16384
#define SM2_FLOATS 36864
#define SM2_BYTES  (SM2_FLOATS * 4)

__device__ __forceinline__ float gelu_erf(float x) {
    return 0.5f * x * (1.0f + erff(x * 0.70710678118654752440f));
}
__device__ __forceinline__ void fma2(u64& d, u64 a, u64 b) {
    asm("fma.rn.f32x2 %0, %1, %2, %0;" : "+l"(d) : "l"(a), "l"(b));
}
__device__ __forceinline__ void lds2(u64& a, u64& b, unsigned addr) {
    asm volatile("ld.shared.v2.b64 {%0,%1}, [%2];" : "=l"(a), "=l"(b) : "r"(addr));
}
__device__ __forceinline__ float hadd(u64 p) {
    float lo, hi;
    asm("mov.b64 {%0,%1}, %2;" : "=f"(lo), "=f"(hi) : "l"(p));
    return lo + hi;
}

__device__ __forceinline__ void ln_stats(const float* v, float* sStats, int o, int tid) {
    if (tid < 32) {
        float s = 0.f, s2 = 0.f;
        #pragma unroll
        for (int i = 0; i < 4; ++i) {
            float x = v[tid + i * 32];
            s += x; s2 += x * x;
        }
        #pragma unroll
        for (int off = 16; off > 0; off >>= 1) {
            s  += __shfl_xor_sync(0xffffffffu, s,  off);
            s2 += __shfl_xor_sync(0xffffffffu, s2, off);
        }
        if (tid == 0) {
            float mean = s * (1.0f / 128.0f);
            float var  = s2 * (1.0f / 128.0f) - mean * mean;
            sStats[o]     = mean;
            sStats[o + 1] = rsqrtf(var + 1e-5f);
        }
    }
}

// stage 16384 contiguous floats into sW
__device__ __forceinline__ void stage_w(float* sW, const float2* src, int tid) {
    const float4* s4 = (const float4*)src;
    float4* d4 = (float4*)sW;
    #pragma unroll
    for (int i = 0; i < 16; ++i) d4[i * NT + tid] = s4[i * NT + tid];
}

// one 2-k2 step (4 k): 6 m-rows, 4 n per lane
#define INNER6(XB, XSTRIDE, WB)                                        \
  {                                                                    \
    u64 w00, w01, w02, w03, w10, w11, w12, w13;                        \
    lds2(w00, w01, (WB));        lds2(w02, w03, (WB) + 16);            \
    lds2(w10, w11, (WB) + 1024); lds2(w12, w13, (WB) + 1040);          \
    _Pragma("unroll")                                                  \
    for (int j = 0; j < 6; ++j) {                                      \
      u64 xa, xb; lds2(xa, xb, (XB) + j * (XSTRIDE));                  \
      fma2(acc[j][0], xa, w00); fma2(acc[j][1], xa, w01);              \
      fma2(acc[j][2], xa, w02); fma2(acc[j][3], xa, w03);              \
      fma2(acc[j][0], xb, w10); fma2(acc[j][1], xb, w11);              \
      fma2(acc[j][2], xb, w12); fma2(acc[j][3], xb, w13);              \
    }                                                                  \
  }

#define INNER4(XB, XSTRIDE, WB)                                        \
  {                                                                    \
    u64 w00, w01, w02, w03, w10, w11, w12, w13;                        \
    lds2(w00, w01, (WB));        lds2(w02, w03, (WB) + 16);            \
    lds2(w10, w11, (WB) + 1024); lds2(w12, w13, (WB) + 1040);          \
    _Pragma("unroll")                                                  \
    for (int j = 0; j < 4; ++j) {                                      \
      u64 xa, xb; lds2(xa, xb, (XB) + j * (XSTRIDE));                  \
      fma2(acc[j][0], xa, w00); fma2(acc[j][1], xa, w01);              \
      fma2(acc[j][2], xa, w02); fma2(acc[j][3], xa, w03);              \
      fma2(acc[j][0], xb, w10); fma2(acc[j][1], xb, w11);              \
      fma2(acc[j][2], xb, w12); fma2(acc[j][3], xb, w13);              \
    }                                                                  \
  }

// =========================================================================
// Kernel 1: per node — edge MLP (3 layers), masked aggregate, LN1 -> g_Hbuf
// 2 CTAs/SM: X is k-tiled [48][128], weight tile 64 KB, Y2 reuses X region.
// =========================================================================
__global__ void __launch_bounds__(NT, 2)
edge_mlp_kernel(
    const float* __restrict__ h_V, const float* __restrict__ h_E,
    const float* __restrict__ mask_attend,
    const float* __restrict__ W1_b, const float* __restrict__ W2_b,
    const float* __restrict__ W3_b,
    const float* __restrict__ ln1_g, const float* __restrict__ ln1_b)
{
    extern __shared__ float sm[];
    const int tid = threadIdx.x;
    const int tx  = tid & 31;      // lane: n = 4*tx .. 4*tx+3
    const int ty  = tid >> 5;      // warp: m = 6*ty .. 6*ty+5
    const int m0  = ty * 6;
    const int ng  = blockIdx.x;

    const unsigned sbase = (unsigned)__cvta_generic_to_shared(sm);
    float* sA  = sm + OFF_A;
    float* sW  = sm + OFF_W;
    float* sY1 = sm + OFF_Y1;

    u64 acc[6][4];
    const unsigned wl  = sbase + OFF_W * 4 + tx * 32;
    const unsigned xbA = sbase + OFF_A * 4 + m0 * 512;
    const unsigned xbY = sbase + OFF_Y1 * 4 + m0 * 512;

    const float4* hv4 = (const float4*)(h_V + (size_t)ng * Hdim);
    const float4* he4 = (const float4*)(h_E + (size_t)ng * (KNB * NINdim));

    // ================= Phase B: Y1 = gelu(X @ W1^T + b1), k-tiled x4 =================
    #pragma unroll
    for (int j = 0; j < 6; ++j)
        #pragma unroll
        for (int c = 0; c < 4; ++c) acc[j][c] = 0ULL;

    for (int kt = 0; kt < 4; ++kt) {
        __syncthreads();
        // stage X tile [48][128]: kt0 = h_V broadcast, kt>=1 = h_E slice
        #pragma unroll
        for (int it = 0; it < 6; ++it) {
            int idx = it * NT + tid;
            int m = idx >> 5, q = idx & 31;
            ((float4*)sA)[m * 32 + q] =
                (kt == 0) ? hv4[q] : he4[m * 96 + (kt - 1) * 32 + q];
        }
        stage_w(sW, g_W1p + kt * 8192, tid);
        __syncthreads();
        #pragma unroll 2
        for (int it = 0; it < 32; ++it)
            INNER6(xbA + it * 16, 512, wl + it * 2048);
    }
    // epilogue B -> Y1
    {
        float4 bv = ((const float4*)W1_b)[tx];
        #pragma unroll
        for (int j = 0; j < 6; ++j) {
            float4 r;
            r.x = gelu_erf(hadd(acc[j][0]) + bv.x);
            r.y = gelu_erf(hadd(acc[j][1]) + bv.y);
            r.z = gelu_erf(hadd(acc[j][2]) + bv.z);
            r.w = gelu_erf(hadd(acc[j][3]) + bv.w);
            *(float4*)(sY1 + (m0 + j) * 128 + 4 * tx) = r;
            acc[j][0] = acc[j][1] = acc[j][2] = acc[j][3] = 0ULL;
        }
    }
    __syncthreads();

    // ================= Phase C: Y2 = gelu(Y1 @ W2^T + b2) =================
    stage_w(sW, g_W2p, tid);
    __syncthreads();
    #pragma unroll 2
    for (int it = 0; it < 32; ++it)
        INNER6(xbY + it * 16, 512, wl + it * 2048);
    // epilogue C -> sA (X tile region is free)
    {
        float4 bv = ((const float4*)W2_b)[tx];
        #pragma unroll
        for (int j = 0; j < 6; ++j) {
            float4 r;
            r.x = gelu_erf(hadd(acc[j][0]) + bv.x);
            r.y = gelu_erf(hadd(acc[j][1]) + bv.y);
            r.z = gelu_erf(hadd(acc[j][2]) + bv.z);
            r.w = gelu_erf(hadd(acc[j][3]) + bv.w);
            *(float4*)(sA + (m0 + j) * 128 + 4 * tx) = r;
            acc[j][0] = acc[j][1] = acc[j][2] = acc[j][3] = 0ULL;
        }
    }
    __syncthreads();

    // ================= Phase D: msg = Y2 @ W3^T + b3, masked sum =================
    stage_w(sW, g_W3p, tid);
    __syncthreads();
    #pragma unroll 2
    for (int it = 0; it < 32; ++it)
        INNER6(xbA + it * 16, 512, wl + it * 2048);

    float* sRed = sm + T_RED;
    {
        float4 bv = ((const float4*)W3_b)[tx];
        float p0 = 0.f, p1 = 0.f, p2 = 0.f, p3 = 0.f;
        #pragma unroll
        for (int j = 0; j < 6; ++j) {
            float ma = mask_attend[(size_t)ng * KNB + m0 + j];
            p0 = fmaf(ma, hadd(acc[j][0]) + bv.x, p0);
            p1 = fmaf(ma, hadd(acc[j][1]) + bv.y, p1);
            p2 = fmaf(ma, hadd(acc[j][2]) + bv.z, p2);
            p3 = fmaf(ma, hadd(acc[j][3]) + bv.w, p3);
        }
        __syncthreads();   // Y1 region now becomes RED scratch
        *(float4*)(sRed + ty * 128 + 4 * tx) = make_float4(p0, p1, p2, p3);
    }
    __syncthreads();

    float* sVec   = sm + T_VEC;
    float* sStats = sm + T_ST;
    if (tid < 128) {
        float dh = 0.f;
        #pragma unroll
        for (int g = 0; g < 8; ++g) dh += sRed[g * 128 + tid];
        dh *= (1.0f / 30.0f);
        sVec[tid] = h_V[(size_t)ng * Hdim + tid] + dh;
    }
    __syncthreads();
    ln_stats(sVec, sStats, 0, tid);
    __syncthreads();
    if (tid < 128) {
        g_Hbuf[(size_t)ng * Hdim + tid] =
            (sVec[tid] - sStats[0]) * sStats[1] * ln1_g[tid] + ln1_b[tid];
    }
}

// =========================================================================
// Kernel 2: batched FFN + LN2 + mask (32 nodes per CTA)
// =========================================================================
__global__ void __launch_bounds__(NT, 1)
ffn_kernel(const float* __restrict__ mask_V,
           const float* __restrict__ Win_b, const float* __restrict__ Wout_b,
           const float* __restrict__ ln2_g, const float* __restrict__ ln2_b,
           float* __restrict__ out)
{
    extern __shared__ float sm[];
    const int tid = threadIdx.x;
    const int tx  = tid & 31;
    const int ty  = tid >> 5;
    const int m0  = ty * 4;             // 4 nodes per warp
    const int nb  = blockIdx.x * 32;    // node base

    const unsigned sbase = (unsigned)__cvta_generic_to_shared(sm);
    float* sH = sm + K2_H;
    float* sW = sm + K2_W;
    float* sF = sm + K2_F;
    const unsigned wl = sbase + K2_W * 4 + tx * 32;

    // stage H [32][128]
    {
        const float4* src = (const float4*)(g_Hbuf + (size_t)nb * Hdim);
        float4* dst = (float4*)sH;
        #pragma unroll
        for (int i = 0; i < 4; ++i) dst[i * NT + tid] = src[i * NT + tid];
    }

    u64 acc[4][4];

    // ---- GEMM1: F = gelu(H @ Win^T + bin), n-blocked over 512 ----
    for (int nblk = 0; nblk < 4; ++nblk) {
        __syncthreads();
        {
            const float4* s4 = (const float4*)g_Winp;
            float4* d4 = (float4*)sW;
            #pragma unroll
            for (int i = 0; i < 16; ++i) {
                int id4 = i * NT + tid;
                int k2 = id4 >> 6, c4 = id4 & 63;
                d4[id4] = s4[k2 * 256 + nblk * 64 + c4];
            }
        }
        __syncthreads();
        #pragma unroll
        for (int j = 0; j < 4; ++j)
            #pragma unroll
            for (int c = 0; c < 4; ++c) acc[j][c] = 0ULL;
        {
            const unsigned xrow = sbase + K2_H * 4 + m0 * 512;
            #pragma unroll 2
            for (int it = 0; it < 32; ++it)
                INNER4(xrow + it * 16, 512, wl + it * 2048);
        }
        float4 bv = ((const float4*)Win_b)[nblk * 32 + tx];
        #pragma unroll
        for (int j = 0; j < 4; ++j) {
            float4 r;
            r.x = gelu_erf(hadd(acc[j][0]) + bv.x);
            r.y = gelu_erf(hadd(acc[j][1]) + bv.y);
            r.z = gelu_erf(hadd(acc[j][2]) + bv.z);
            r.w = gelu_erf(hadd(acc[j][3]) + bv.w);
            *(float4*)(sF + (m0 + j) * 512 + nblk * 128 + 4 * tx) = r;
        }
    }

    // ---- GEMM2: O = F @ Wout^T ----
    #pragma unroll
    for (int j = 0; j < 4; ++j)
        #pragma unroll
        for (int c = 0; c < 4; ++c) acc[j][c] = 0ULL;
    for (int kt = 0; kt < 4; ++kt) {
        __syncthreads();
        stage_w(sW, g_Woutp + kt * 8192, tid);
        __syncthreads();
        const unsigned xrow = sbase + K2_F * 4 + m0 * 2048;
        #pragma unroll 2
        for (int it = 0; it < 32; ++it)
            INNER4(xrow + kt * 512 + it * 16, 2048, wl + it * 2048);
    }

    // ---- residual + LN2 + mask, per warp row (shfl) ----
    {
        float4 bv = ((const float4*)Wout_b)[tx];
        float4 gv = ((const float4*)ln2_g)[tx];
        float4 lb = ((const float4*)ln2_b)[tx];
        #pragma unroll
        for (int j = 0; j < 4; ++j) {
            const float* hrow = sH + (m0 + j) * 128 + 4 * tx;
            float v0 = hadd(acc[j][0]) + bv.x + hrow[0];
            float v1 = hadd(acc[j][1]) + bv.y + hrow[1];
            float v2 = hadd(acc[j][2]) + bv.z + hrow[2];
            float v3 = hadd(acc[j][3]) + bv.w + hrow[3];
            float s  = v0 + v1 + v2 + v3;
            float s2 = v0 * v0 + v1 * v1 + v2 * v2 + v3 * v3;
            #pragma unroll
            for (int off = 16; off > 0; off >>= 1) {
                s  += __shfl_xor_sync(0xffffffffu, s,  off);
                s2 += __shfl_xor_sync(0xffffffffu, s2, off);
            }
            float mean = s * (1.0f / 128.0f);
            float rstd = rsqrtf(s2 * (1.0f / 128.0f) - mean * mean + 1e-5f);
            float mv = mask_V[nb + m0 + j];
            float4 r;
            r.x = mv * ((v0 - mean) * rstd * gv.x + lb.x);
            r.y = mv * ((v1 - mean) * rstd * gv.y + lb.y);
            r.z = mv * ((v2 - mean) * rstd * gv.z + lb.z);
            r.w = mv * ((v3 - mean) * rstd * gv.w + lb.w);
            *(float4*)(out + (size_t)(nb + m0 + j) * Hdim + 4 * tx) = r;
        }
    }
}

extern "C" void kernel_launch(void* const* d_in, const int* in_sizes, int n_in,
                              void* d_out, int out_size) {
    const float* h_V         = (const float*)d_in[0];
    const float* h_E         = (const float*)d_in[1];
    const float* mask_V      = (const float*)d_in[2];
    const float* mask_attend = (const float*)d_in[3];
    const float* W1_w        = (const float*)d_in[4];
    const float* W1_b        = (const float*)d_in[5];
    const float* W2_w        = (const float*)d_in[6];
    const float* W2_b        = (const float*)d_in[7];
    const float* W3_w        = (const float*)d_in[8];
    const float* W3_b        = (const float*)d_in[9];
    const float* ln1_g       = (const float*)d_in[10];
    const float* ln1_b       = (const float*)d_in[11];
    const float* ln2_g       = (const float*)d_in[12];
    const float* ln2_b       = (const float*)d_in[13];
    const float* Win_w       = (const float*)d_in[14];
    const float* Win_b       = (const float*)d_in[15];
    const float* Wout_w      = (const float*)d_in[16];
    const float* Wout_b      = (const float*)d_in[17];

    int nodes = in_sizes[0] / Hdim;   // 4096

    prep_weights<<<448, 256>>>(W1_w, W2_w, W3_w, Win_w, Wout_w);

    cudaFuncSetAttribute(edge_mlp_kernel,
                         cudaFuncAttributeMaxDynamicSharedMemorySize, SM1_BYTES);
    cudaFuncSetAttribute(ffn_kernel,
                         cudaFuncAttributeMaxDynamicSharedMemorySize, SM2_BYTES);

    edge_mlp_kernel<<<nodes, NT, SM1_BYTES>>>(
        h_V, h_E, mask_attend, W1_b, W2_b, W3_b, ln1_g, ln1_b);

    ffn_kernel<<<nodes / 32, NT, SM2_BYTES>>>(
        mask_V, Win_b, Wout_b, ln2_g, ln2_b, (float*)d_out);
}

// round 7
// speedup vs baseline: 1.8112x; 1.0874x over previous
#include <cuda_runtime.h>
#include <math.h>

#define Hdim   128
#define NINdim 384
#define CIN    512
#define KNB    48
#define FFdim  512
#define NT     256

typedef unsigned long long u64;

// ---------------- pre-paired weights (prep kernel output) ----------------
// Wp[k2][n] = (W[n][2k2], W[n][2k2+1])  -- k-pair interleaved, n contiguous
__device__ float2 g_W1p[256 * 128];
__device__ float2 g_W2p[64 * 128];
__device__ float2 g_W3p[64 * 128];
__device__ float2 g_Winp[64 * 512];    // [k2][f]
__device__ float2 g_Woutp[256 * 128];  // [k2][n]
__device__ float  g_Hbuf[4096 * 128];  // post-LN1 hidden

__global__ void prep_weights(const float* __restrict__ W1_w,
                             const float* __restrict__ W2_w,
                             const float* __restrict__ W3_w,
                             const float* __restrict__ Win_w,
                             const float* __restrict__ Wout_w) {
    int idx = blockIdx.x * blockDim.x + threadIdx.x;
    if (idx < 32768) {                         // W1p: k2<256, n<128
        int k2 = idx >> 7, n = idx & 127;
        g_W1p[idx] = make_float2(W1_w[n * 512 + 2 * k2], W1_w[n * 512 + 2 * k2 + 1]);
    } else if (idx < 40960) {                  // W2p: k2<64
        int i = idx - 32768;
        int k2 = i >> 7, n = i & 127;
        g_W2p[i] = make_float2(W2_w[n * 128 + 2 * k2], W2_w[n * 128 + 2 * k2 + 1]);
    } else if (idx < 49152) {                  // W3p
        int i = idx - 40960;
        int k2 = i >> 7, n = i & 127;
        g_W3p[i] = make_float2(W3_w[n * 128 + 2 * k2], W3_w[n * 128 + 2 * k2 + 1]);
    } else if (idx < 81920) {                  // Winp: k2<64, f<512
        int i = idx - 49152;
        int k2 = i >> 9, f = i & 511;
        g_Winp[i] = make_float2(Win_w[f * 128 + 2 * k2], Win_w[f * 128 + 2 * k2 + 1]);
    } else if (idx < 114688) {                 // Woutp: k2<256, n<128
        int i = idx - 81920;
        int k2 = i >> 7, n = i & 127;
        g_Woutp[i] = make_float2(Wout_w[n * 512 + 2 * k2], Wout_w[n * 512 + 2 * k2 + 1]);
    }
}

// ---------------- kernel-1 shared layout (floats), 2 CTAs/SM ----------------
#define OFF_A   0        // X k-tile [48][128] in B; Y2 in C-out/D     6144
#define OFF_W   6144     // weight tile (64 k2 x 128 n float2)        16384
#define OFF_Y1  22528    // Y1 [48][128]; tail scratch after D         6144
#define T_RED   22528
#define T_VEC   23552
#define T_ST    23680
#define SM1_FLOATS 28672
#define SM1_BYTES  (SM1_FLOATS * 4)     // 114688 B -> 2 CTAs/SM

// ---------------- kernel-2 shared layout ----------------
#define K2_H   0         // H [32][128]            4096
#define K2_W   4096      // weight tile           16384
#define K2_F   20480     // F [32][512]           16384
#define K2_O   36864     // O [32][128]            4096
#define SM2_FLOATS 40960
#define SM2_BYTES  (SM2_FLOATS * 4)

__device__ __forceinline__ float gelu_erf(float x) {
    return 0.5f * x * (1.0f + erff(x * 0.70710678118654752440f));
}
__device__ __forceinline__ void fma2(u64& d, u64 a, u64 b) {
    asm("fma.rn.f32x2 %0, %1, %2, %0;" : "+l"(d) : "l"(a), "l"(b));
}
__device__ __forceinline__ void lds2(u64& a, u64& b, unsigned addr) {
    asm volatile("ld.shared.v2.b64 {%0,%1}, [%2];" : "=l"(a), "=l"(b) : "r"(addr));
}
__device__ __forceinline__ float hadd(u64 p) {
    float lo, hi;
    asm("mov.b64 {%0,%1}, %2;" : "=f"(lo), "=f"(hi) : "l"(p));
    return lo + hi;
}

__device__ __forceinline__ void ln_stats(const float* v, float* sStats, int o, int tid) {
    if (tid < 32) {
        float s = 0.f, s2 = 0.f;
        #pragma unroll
        for (int i = 0; i < 4; ++i) {
            float x = v[tid + i * 32];
            s += x; s2 += x * x;
        }
        #pragma unroll
        for (int off = 16; off > 0; off >>= 1) {
            s  += __shfl_xor_sync(0xffffffffu, s,  off);
            s2 += __shfl_xor_sync(0xffffffffu, s2, off);
        }
        if (tid == 0) {
            float mean = s * (1.0f / 128.0f);
            float var  = s2 * (1.0f / 128.0f) - mean * mean;
            sStats[o]     = mean;
            sStats[o + 1] = rsqrtf(var + 1e-5f);
        }
    }
}

// stage 16384 contiguous floats into sW
__device__ __forceinline__ void stage_w(float* sW, const float2* src, int tid) {
    const float4* s4 = (const float4*)src;
    float4* d4 = (float4*)sW;
    #pragma unroll
    for (int i = 0; i < 16; ++i) d4[i * NT + tid] = s4[i * NT + tid];
}

// One 2-k2 step (4 k). Warp tile: J m-rows x 64 n; lane: J m x 2 n.
// WB points at this lane's 2n within k2 row; k2 row stride = 1024 B.
#define INNER(J, XB, XSTRIDE, WB)                                      \
  {                                                                    \
    u64 wa0, wa1, wb0, wb1;                                            \
    lds2(wa0, wa1, (WB));                                              \
    lds2(wb0, wb1, (WB) + 1024);                                       \
    _Pragma("unroll")                                                  \
    for (int j = 0; j < (J); ++j) {                                    \
      u64 xa, xb; lds2(xa, xb, (XB) + j * (XSTRIDE));                  \
      fma2(acc[j][0], xa, wa0); fma2(acc[j][1], xa, wa1);              \
      fma2(acc[j][0], xb, wb0); fma2(acc[j][1], xb, wb1);              \
    }                                                                  \
  }

// =========================================================================
// Kernel 1: per node — edge MLP (3 layers), masked aggregate, LN1 -> g_Hbuf
// Warps: (wm 0..3) x (wn 0..1); warp tile 12 m x 64 n.
// =========================================================================
__global__ void __launch_bounds__(NT, 2)
edge_mlp_kernel(
    const float* __restrict__ h_V, const float* __restrict__ h_E,
    const float* __restrict__ mask_attend,
    const float* __restrict__ W1_b, const float* __restrict__ W2_b,
    const float* __restrict__ W3_b,
    const float* __restrict__ ln1_g, const float* __restrict__ ln1_b)
{
    extern __shared__ float sm[];
    const int tid = threadIdx.x;
    const int tx  = tid & 31;
    const int ty  = tid >> 5;
    const int wm  = ty >> 1;            // 0..3 -> m block of 12
    const int wn  = ty & 1;             // 0..1 -> n block of 64
    const int m0  = wm * 12;
    const int n0  = wn * 64 + 2 * tx;   // this lane's first n
    const int ng  = blockIdx.x;

    const unsigned sbase = (unsigned)__cvta_generic_to_shared(sm);
    float* sA  = sm + OFF_A;
    float* sY1 = sm + OFF_Y1;
    float* sW  = sm + OFF_W;

    u64 acc[12][2];
    const unsigned wl  = sbase + OFF_W * 4 + n0 * 8;          // lane weight addr
    const unsigned xbA = sbase + OFF_A * 4 + m0 * 512;
    const unsigned xbY = sbase + OFF_Y1 * 4 + m0 * 512;

    const float4* hv4 = (const float4*)(h_V + (size_t)ng * Hdim);
    const float4* he4 = (const float4*)(h_E + (size_t)ng * (KNB * NINdim));

    // ================= Phase B: Y1 = gelu(X @ W1^T + b1), k-tiled x4 =================
    #pragma unroll
    for (int j = 0; j < 12; ++j) { acc[j][0] = 0ULL; acc[j][1] = 0ULL; }

    for (int kt = 0; kt < 4; ++kt) {
        __syncthreads();
        #pragma unroll
        for (int it = 0; it < 6; ++it) {
            int idx = it * NT + tid;
            int m = idx >> 5, q = idx & 31;
            ((float4*)sA)[m * 32 + q] =
                (kt == 0) ? hv4[q] : he4[m * 96 + (kt - 1) * 32 + q];
        }
        stage_w(sW, g_W1p + kt * 8192, tid);
        __syncthreads();
        #pragma unroll 2
        for (int it = 0; it < 32; ++it)
            INNER(12, xbA + it * 16, 512, wl + it * 2048);
    }
    {
        float2 bv = *(const float2*)(W1_b + n0);
        #pragma unroll
        for (int j = 0; j < 12; ++j) {
            float2 r;
            r.x = gelu_erf(hadd(acc[j][0]) + bv.x);
            r.y = gelu_erf(hadd(acc[j][1]) + bv.y);
            *(float2*)(sY1 + (m0 + j) * 128 + n0) = r;
            acc[j][0] = 0ULL; acc[j][1] = 0ULL;
        }
    }
    __syncthreads();

    // ================= Phase C: Y2 = gelu(Y1 @ W2^T + b2) =================
    stage_w(sW, g_W2p, tid);
    __syncthreads();
    #pragma unroll 2
    for (int it = 0; it < 32; ++it)
        INNER(12, xbY + it * 16, 512, wl + it * 2048);
    {
        float2 bv = *(const float2*)(W2_b + n0);
        #pragma unroll
        for (int j = 0; j < 12; ++j) {
            float2 r;
            r.x = gelu_erf(hadd(acc[j][0]) + bv.x);
            r.y = gelu_erf(hadd(acc[j][1]) + bv.y);
            *(float2*)(sA + (m0 + j) * 128 + n0) = r;
            acc[j][0] = 0ULL; acc[j][1] = 0ULL;
        }
    }
    __syncthreads();

    // ================= Phase D: msg = Y2 @ W3^T + b3, masked sum =================
    stage_w(sW, g_W3p, tid);
    __syncthreads();
    #pragma unroll 2
    for (int it = 0; it < 32; ++it)
        INNER(12, xbA + it * 16, 512, wl + it * 2048);

    float* sRed = sm + T_RED;     // [4][128] (per-wm partial sums)
    {
        float2 bv = *(const float2*)(W3_b + n0);
        float p0 = 0.f, p1 = 0.f;
        #pragma unroll
        for (int j = 0; j < 12; ++j) {
            float ma = mask_attend[(size_t)ng * KNB + m0 + j];
            p0 = fmaf(ma, hadd(acc[j][0]) + bv.x, p0);
            p1 = fmaf(ma, hadd(acc[j][1]) + bv.y, p1);
        }
        __syncthreads();          // Y1 region becomes RED scratch
        *(float2*)(sRed + wm * 128 + n0) = make_float2(p0, p1);
    }
    __syncthreads();

    float* sVec   = sm + T_VEC;
    float* sStats = sm + T_ST;
    if (tid < 128) {
        float dh = sRed[tid] + sRed[128 + tid] + sRed[256 + tid] + sRed[384 + tid];
        dh *= (1.0f / 30.0f);
        sVec[tid] = h_V[(size_t)ng * Hdim + tid] + dh;
    }
    __syncthreads();
    ln_stats(sVec, sStats, 0, tid);
    __syncthreads();
    if (tid < 128) {
        g_Hbuf[(size_t)ng * Hdim + tid] =
            (sVec[tid] - sStats[0]) * sStats[1] * ln1_g[tid] + ln1_b[tid];
    }
}

// =========================================================================
// Kernel 2: batched FFN + LN2 + mask (32 nodes per CTA)
// Warps: (wm 0..3) x (wn 0..1); warp tile 8 m x 64 n.
// =========================================================================
__global__ void __launch_bounds__(NT, 1)
ffn_kernel(const float* __restrict__ mask_V,
           const float* __restrict__ Win_b, const float* __restrict__ Wout_b,
           const float* __restrict__ ln2_g, const float* __restrict__ ln2_b,
           float* __restrict__ out)
{
    extern __shared__ float sm[];
    const int tid = threadIdx.x;
    const int tx  = tid & 31;
    const int ty  = tid >> 5;
    const int wm  = ty >> 1;
    const int wn  = ty & 1;
    const int m0  = wm * 8;
    const int n0  = wn * 64 + 2 * tx;
    const int nb  = blockIdx.x * 32;

    const unsigned sbase = (unsigned)__cvta_generic_to_shared(sm);
    float* sH = sm + K2_H;
    float* sW = sm + K2_W;
    float* sF = sm + K2_F;
    float* sO = sm + K2_O;
    const unsigned wl = sbase + K2_W * 4 + n0 * 8;

    // stage H [32][128]
    {
        const float4* src = (const float4*)(g_Hbuf + (size_t)nb * Hdim);
        float4* dst = (float4*)sH;
        #pragma unroll
        for (int i = 0; i < 4; ++i) dst[i * NT + tid] = src[i * NT + tid];
    }

    u64 acc[8][2];

    // ---- GEMM1: F = gelu(H @ Win^T + bin), n-blocked over 512 ----
    for (int nblk = 0; nblk < 4; ++nblk) {
        __syncthreads();
        {
            const float4* s4 = (const float4*)g_Winp;
            float4* d4 = (float4*)sW;
            #pragma unroll
            for (int i = 0; i < 16; ++i) {
                int id4 = i * NT + tid;
                int k2 = id4 >> 6, c4 = id4 & 63;
                d4[id4] = s4[k2 * 256 + nblk * 64 + c4];
            }
        }
        __syncthreads();
        #pragma unroll
        for (int j = 0; j < 8; ++j) { acc[j][0] = 0ULL; acc[j][1] = 0ULL; }
        {
            const unsigned xrow = sbase + K2_H * 4 + m0 * 512;
            #pragma unroll 2
            for (int it = 0; it < 32; ++it)
                INNER(8, xrow + it * 16, 512, wl + it * 2048);
        }
        float2 bv = *(const float2*)(Win_b + nblk * 128 + n0);
        #pragma unroll
        for (int j = 0; j < 8; ++j) {
            float2 r;
            r.x = gelu_erf(hadd(acc[j][0]) + bv.x);
            r.y = gelu_erf(hadd(acc[j][1]) + bv.y);
            *(float2*)(sF + (m0 + j) * 512 + nblk * 128 + n0) = r;
        }
    }

    // ---- GEMM2: O = F @ Wout^T + bout ----
    #pragma unroll
    for (int j = 0; j < 8; ++j) { acc[j][0] = 0ULL; acc[j][1] = 0ULL; }
    for (int kt = 0; kt < 4; ++kt) {
        __syncthreads();
        stage_w(sW, g_Woutp + kt * 8192, tid);
        __syncthreads();
        const unsigned xrow = sbase + K2_F * 4 + m0 * 2048;
        #pragma unroll 2
        for (int it = 0; it < 32; ++it)
            INNER(8, xrow + kt * 512 + it * 16, 2048, wl + it * 2048);
    }
    {
        float2 bv = *(const float2*)(Wout_b + n0);
        #pragma unroll
        for (int j = 0; j < 8; ++j) {
            float2 r;
            r.x = hadd(acc[j][0]) + bv.x;
            r.y = hadd(acc[j][1]) + bv.y;
            *(float2*)(sO + (m0 + j) * 128 + n0) = r;
        }
    }
    __syncthreads();

    // ---- residual + LN2 + mask: warp ty handles rows ty, ty+8, ty+16, ty+24 ----
    #pragma unroll
    for (int rr = 0; rr < 4; ++rr) {
        int r = ty + rr * 8;
        float v[4];
        float s = 0.f, s2 = 0.f;
        #pragma unroll
        for (int i = 0; i < 4; ++i) {
            int n = tx + i * 32;
            v[i] = sH[r * 128 + n] + sO[r * 128 + n];
            s += v[i]; s2 += v[i] * v[i];
        }
        #pragma unroll
        for (int off = 16; off > 0; off >>= 1) {
            s  += __shfl_xor_sync(0xffffffffu, s,  off);
            s2 += __shfl_xor_sync(0xffffffffu, s2, off);
        }
        float mean = s * (1.0f / 128.0f);
        float rstd = rsqrtf(s2 * (1.0f / 128.0f) - mean * mean + 1e-5f);
        float mv = mask_V[nb + r];
        #pragma unroll
        for (int i = 0; i < 4; ++i) {
            int n = tx + i * 32;
            out[(size_t)(nb + r) * Hdim + n] =
                mv * ((v[i] - mean) * rstd * ln2_g[n] + ln2_b[n]);
        }
    }
}

extern "C" void kernel_launch(void* const* d_in, const int* in_sizes, int n_in,
                              void* d_out, int out_size) {
    const float* h_V         = (const float*)d_in[0];
    const float* h_E         = (const float*)d_in[1];
    const float* mask_V      = (const float*)d_in[2];
    const float* mask_attend = (const float*)d_in[3];
    const float* W1_w        = (const float*)d_in[4];
    const float* W1_b        = (const float*)d_in[5];
    const float* W2_w        = (const float*)d_in[6];
    const float* W2_b        = (const float*)d_in[7];
    const float* W3_w        = (const float*)d_in[8];
    const float* W3_b        = (const float*)d_in[9];
    const float* ln1_g       = (const float*)d_in[10];
    const float* ln1_b       = (const float*)d_in[11];
    const float* ln2_g       = (const float*)d_in[12];
    const float* ln2_b       = (const float*)d_in[13];
    const float* Win_w       = (const float*)d_in[14];
    const float* Win_b       = (const float*)d_in[15];
    const float* Wout_w      = (const float*)d_in[16];
    const float* Wout_b      = (const float*)d_in[17];

    int nodes = in_sizes[0] / Hdim;   // 4096

    prep_weights<<<448, 256>>>(W1_w, W2_w, W3_w, Win_w, Wout_w);

    cudaFuncSetAttribute(edge_mlp_kernel,
                         cudaFuncAttributeMaxDynamicSharedMemorySize, SM1_BYTES);
    cudaFuncSetAttribute(ffn_kernel,
                         cudaFuncAttributeMaxDynamicSharedMemorySize, SM2_BYTES);

    edge_mlp_kernel<<<nodes, NT, SM1_BYTES>>>(
        h_V, h_E, mask_attend, W1_b, W2_b, W3_b, ln1_g, ln1_b);

    ffn_kernel<<<nodes / 32, NT, SM2_BYTES>>>(
        mask_V, Win_b, Wout_b, ln2_g, ln2_b, (float*)d_out);
}

// round 8
// speedup vs baseline: 1.8874x; 1.0421x over previous
#include <cuda_runtime.h>
#include <math.h>

#define Hdim   128
#define NINdim 384
#define CIN    512
#define KNB    48
#define FFdim  512
#define NT     256

typedef unsigned long long u64;

// ---------------- pre-paired weights (prep kernel output) ----------------
// Wp[k2][n] = (W[n][2k2], W[n][2k2+1])  -- k-pair interleaved, n contiguous
__device__ float2 g_W1p[256 * 128];
__device__ float2 g_W2p[64 * 128];
__device__ float2 g_W3p[64 * 128];
__device__ float2 g_Winp[64 * 512];    // [k2][f]
__device__ float2 g_Woutp[256 * 128];  // [k2][n]
__device__ float  g_Hbuf[4096 * 128];  // post-LN1 hidden

__global__ void prep_weights(const float* __restrict__ W1_w,
                             const float* __restrict__ W2_w,
                             const float* __restrict__ W3_w,
                             const float* __restrict__ Win_w,
                             const float* __restrict__ Wout_w) {
    int idx = blockIdx.x * blockDim.x + threadIdx.x;
    if (idx < 32768) {                         // W1p: k2<256, n<128
        int k2 = idx >> 7, n = idx & 127;
        g_W1p[idx] = make_float2(W1_w[n * 512 + 2 * k2], W1_w[n * 512 + 2 * k2 + 1]);
    } else if (idx < 40960) {                  // W2p: k2<64
        int i = idx - 32768;
        int k2 = i >> 7, n = i & 127;
        g_W2p[i] = make_float2(W2_w[n * 128 + 2 * k2], W2_w[n * 128 + 2 * k2 + 1]);
    } else if (idx < 49152) {                  // W3p
        int i = idx - 40960;
        int k2 = i >> 7, n = i & 127;
        g_W3p[i] = make_float2(W3_w[n * 128 + 2 * k2], W3_w[n * 128 + 2 * k2 + 1]);
    } else if (idx < 81920) {                  // Winp: k2<64, f<512
        int i = idx - 49152;
        int k2 = i >> 9, f = i & 511;
        g_Winp[i] = make_float2(Win_w[f * 128 + 2 * k2], Win_w[f * 128 + 2 * k2 + 1]);
    } else if (idx < 114688) {                 // Woutp: k2<256, n<128
        int i = idx - 81920;
        int k2 = i >> 7, n = i & 127;
        g_Woutp[i] = make_float2(Wout_w[n * 512 + 2 * k2], Wout_w[n * 512 + 2 * k2 + 1]);
    }
}

// ---------------- kernel-1 shared layout (floats) ----------------
#define OFF_A   0        // X k-tile [48][128] in B; Y2 in C-out/D     6144
#define OFF_Y1  6144     // Y1 [48][128]                               6144
#define T_RED   12288    // [4][128]
#define T_VEC   12800
#define T_ST    12928
#define SM1_FLOATS 12936
#define SM1_BYTES  (SM1_FLOATS * 4)     // ~52 KB

// ---------------- kernel-2 shared layout ----------------
#define K2_H   0         // H [32][128]            4096
#define K2_F   4096      // F [32][512]           16384
#define K2_O   20480     // O [32][128]            4096
#define SM2_FLOATS 24576
#define SM2_BYTES  (SM2_FLOATS * 4)

__device__ __forceinline__ float gelu_erf(float x) {
    return 0.5f * x * (1.0f + erff(x * 0.70710678118654752440f));
}
__device__ __forceinline__ void fma2(u64& d, u64 a, u64 b) {
    asm("fma.rn.f32x2 %0, %1, %2, %0;" : "+l"(d) : "l"(a), "l"(b));
}
__device__ __forceinline__ void lds2(u64& a, u64& b, unsigned addr) {
    asm volatile("ld.shared.v2.b64 {%0,%1}, [%2];" : "=l"(a), "=l"(b) : "r"(addr));
}
__device__ __forceinline__ float hadd(u64 p) {
    float lo, hi;
    asm("mov.b64 {%0,%1}, %2;" : "=f"(lo), "=f"(hi) : "l"(p));
    return lo + hi;
}

__device__ __forceinline__ void ln_stats(const float* v, float* sStats, int o, int tid) {
    if (tid < 32) {
        float s = 0.f, s2 = 0.f;
        #pragma unroll
        for (int i = 0; i < 4; ++i) {
            float x = v[tid + i * 32];
            s += x; s2 += x * x;
        }
        #pragma unroll
        for (int off = 16; off > 0; off >>= 1) {
            s  += __shfl_xor_sync(0xffffffffu, s,  off);
            s2 += __shfl_xor_sync(0xffffffffu, s2, off);
        }
        if (tid == 0) {
            float mean = s * (1.0f / 128.0f);
            float var  = s2 * (1.0f / 128.0f) - mean * mean;
            sStats[o]     = mean;
            sStats[o + 1] = rsqrtf(var + 1e-5f);
        }
    }
}

// One 2-k2 step (4 k). Weights direct from global (L1-resident tile).
// WP: float* at this lane's (k2, n0); WROWF: floats per k2 row.
#define INNERG(J, XB, XSTRIDE, WP, WROWF)                              \
  {                                                                    \
    ulonglong2 va = __ldg((const ulonglong2*)(WP));                    \
    ulonglong2 vb = __ldg((const ulonglong2*)((WP) + (WROWF)));        \
    _Pragma("unroll")                                                  \
    for (int j = 0; j < (J); ++j) {                                    \
      u64 xa, xb; lds2(xa, xb, (XB) + j * (XSTRIDE));                  \
      fma2(acc[j][0], xa, va.x); fma2(acc[j][1], xa, va.y);            \
      fma2(acc[j][0], xb, vb.x); fma2(acc[j][1], xb, vb.y);            \
    }                                                                  \
  }

// =========================================================================
// Kernel 1: per node — edge MLP (3 layers), masked aggregate, LN1 -> g_Hbuf
// Warps: (wm 0..3) x (wn 0..1); warp tile 12 m x 64 n. Weights via __ldg.
// =========================================================================
__global__ void __launch_bounds__(NT, 2)
edge_mlp_kernel(
    const float* __restrict__ h_V, const float* __restrict__ h_E,
    const float* __restrict__ mask_attend,
    const float* __restrict__ W1_b, const float* __restrict__ W2_b,
    const float* __restrict__ W3_b,
    const float* __restrict__ ln1_g, const float* __restrict__ ln1_b)
{
    extern __shared__ float sm[];
    const int tid = threadIdx.x;
    const int tx  = tid & 31;
    const int ty  = tid >> 5;
    const int wm  = ty >> 1;            // 0..3 -> m block of 12
    const int wn  = ty & 1;             // 0..1 -> n block of 64
    const int m0  = wm * 12;
    const int n0  = wn * 64 + 2 * tx;   // lane's first n
    const int ng  = blockIdx.x;

    const unsigned sbase = (unsigned)__cvta_generic_to_shared(sm);
    float* sA  = sm + OFF_A;
    float* sY1 = sm + OFF_Y1;

    u64 acc[12][2];
    const unsigned xbA = sbase + OFF_A * 4 + m0 * 512;
    const unsigned xbY = sbase + OFF_Y1 * 4 + m0 * 512;

    const float* gW1 = (const float*)g_W1p + 2 * n0;   // + k2*256
    const float* gW2 = (const float*)g_W2p + 2 * n0;
    const float* gW3 = (const float*)g_W3p + 2 * n0;

    const float4* hv4 = (const float4*)(h_V + (size_t)ng * Hdim);
    const float4* he4 = (const float4*)(h_E + (size_t)ng * (KNB * NINdim));

    // ================= Phase B: Y1 = gelu(X @ W1^T + b1), k-tiled x4 =================
    #pragma unroll
    for (int j = 0; j < 12; ++j) { acc[j][0] = 0ULL; acc[j][1] = 0ULL; }

    for (int kt = 0; kt < 4; ++kt) {
        __syncthreads();
        #pragma unroll
        for (int it = 0; it < 6; ++it) {
            int idx = it * NT + tid;
            int m = idx >> 5, q = idx & 31;
            ((float4*)sA)[m * 32 + q] =
                (kt == 0) ? hv4[q] : he4[m * 96 + (kt - 1) * 32 + q];
        }
        __syncthreads();
        const float* wp = gW1 + kt * 16384;
        #pragma unroll 4
        for (int it = 0; it < 32; ++it)
            INNERG(12, xbA + it * 16, 512, wp + it * 512, 256);
    }
    {
        float2 bv = *(const float2*)(W1_b + n0);
        #pragma unroll
        for (int j = 0; j < 12; ++j) {
            float2 r;
            r.x = gelu_erf(hadd(acc[j][0]) + bv.x);
            r.y = gelu_erf(hadd(acc[j][1]) + bv.y);
            *(float2*)(sY1 + (m0 + j) * 128 + n0) = r;
            acc[j][0] = 0ULL; acc[j][1] = 0ULL;
        }
    }
    __syncthreads();

    // ================= Phase C: Y2 = gelu(Y1 @ W2^T + b2) =================
    #pragma unroll 4
    for (int it = 0; it < 32; ++it)
        INNERG(12, xbY + it * 16, 512, gW2 + it * 512, 256);
    {
        float2 bv = *(const float2*)(W2_b + n0);
        #pragma unroll
        for (int j = 0; j < 12; ++j) {
            float2 r;
            r.x = gelu_erf(hadd(acc[j][0]) + bv.x);
            r.y = gelu_erf(hadd(acc[j][1]) + bv.y);
            *(float2*)(sA + (m0 + j) * 128 + n0) = r;
            acc[j][0] = 0ULL; acc[j][1] = 0ULL;
        }
    }
    __syncthreads();

    // ================= Phase D: msg = Y2 @ W3^T + b3, masked sum =================
    #pragma unroll 4
    for (int it = 0; it < 32; ++it)
        INNERG(12, xbA + it * 16, 512, gW3 + it * 512, 256);

    float* sRed = sm + T_RED;     // [4][128] per-wm partials
    {
        float2 bv = *(const float2*)(W3_b + n0);
        float p0 = 0.f, p1 = 0.f;
        #pragma unroll
        for (int j = 0; j < 12; ++j) {
            float ma = mask_attend[(size_t)ng * KNB + m0 + j];
            p0 = fmaf(ma, hadd(acc[j][0]) + bv.x, p0);
            p1 = fmaf(ma, hadd(acc[j][1]) + bv.y, p1);
        }
        *(float2*)(sRed + wm * 128 + n0) = make_float2(p0, p1);
    }
    __syncthreads();

    float* sVec   = sm + T_VEC;
    float* sStats = sm + T_ST;
    if (tid < 128) {
        float dh = sRed[tid] + sRed[128 + tid] + sRed[256 + tid] + sRed[384 + tid];
        dh *= (1.0f / 30.0f);
        sVec[tid] = h_V[(size_t)ng * Hdim + tid] + dh;
    }
    __syncthreads();
    ln_stats(sVec, sStats, 0, tid);
    __syncthreads();
    if (tid < 128) {
        g_Hbuf[(size_t)ng * Hdim + tid] =
            (sVec[tid] - sStats[0]) * sStats[1] * ln1_g[tid] + ln1_b[tid];
    }
}

// =========================================================================
// Kernel 2: batched FFN + LN2 + mask (32 nodes per CTA)
// Warps: (wm 0..3) x (wn 0..1); warp tile 8 m x 64 n. Weights via __ldg.
// =========================================================================
__global__ void __launch_bounds__(NT, 1)
ffn_kernel(const float* __restrict__ mask_V,
           const float* __restrict__ Win_b, const float* __restrict__ Wout_b,
           const float* __restrict__ ln2_g, const float* __restrict__ ln2_b,
           float* __restrict__ out)
{
    extern __shared__ float sm[];
    const int tid = threadIdx.x;
    const int tx  = tid & 31;
    const int ty  = tid >> 5;
    const int wm  = ty >> 1;
    const int wn  = ty & 1;
    const int m0  = wm * 8;
    const int n0  = wn * 64 + 2 * tx;
    const int nb  = blockIdx.x * 32;

    const unsigned sbase = (unsigned)__cvta_generic_to_shared(sm);
    float* sH = sm + K2_H;
    float* sF = sm + K2_F;
    float* sO = sm + K2_O;

    const float* gWin  = (const float*)g_Winp;    // [k2][512] pairs
    const float* gWout = (const float*)g_Woutp + 2 * n0;

    // stage H [32][128]
    {
        const float4* src = (const float4*)(g_Hbuf + (size_t)nb * Hdim);
        float4* dst = (float4*)sH;
        #pragma unroll
        for (int i = 0; i < 4; ++i) dst[i * NT + tid] = src[i * NT + tid];
    }
    __syncthreads();

    u64 acc[8][2];

    // ---- GEMM1: F = gelu(H @ Win^T + bin), n-blocked over 512 ----
    for (int nblk = 0; nblk < 4; ++nblk) {
        #pragma unroll
        for (int j = 0; j < 8; ++j) { acc[j][0] = 0ULL; acc[j][1] = 0ULL; }
        {
            const unsigned xrow = sbase + K2_H * 4 + m0 * 512;
            const float* wp = gWin + nblk * 256 + 2 * n0;   // f = nblk*128 + n0
            #pragma unroll 4
            for (int it = 0; it < 32; ++it)
                INNERG(8, xrow + it * 16, 512, wp + it * 2048, 1024);
        }
        float2 bv = *(const float2*)(Win_b + nblk * 128 + n0);
        #pragma unroll
        for (int j = 0; j < 8; ++j) {
            float2 r;
            r.x = gelu_erf(hadd(acc[j][0]) + bv.x);
            r.y = gelu_erf(hadd(acc[j][1]) + bv.y);
            *(float2*)(sF + (m0 + j) * 512 + nblk * 128 + n0) = r;
        }
    }
    __syncthreads();

    // ---- GEMM2: O = F @ Wout^T + bout ----
    #pragma unroll
    for (int j = 0; j < 8; ++j) { acc[j][0] = 0ULL; acc[j][1] = 0ULL; }
    for (int kt = 0; kt < 4; ++kt) {
        const unsigned xrow = sbase + K2_F * 4 + m0 * 2048;
        const float* wp = gWout + kt * 16384;
        #pragma unroll 4
        for (int it = 0; it < 32; ++it)
            INNERG(8, xrow + kt * 512 + it * 16, 2048, wp + it * 512, 256);
    }
    {
        float2 bv = *(const float2*)(Wout_b + n0);
        #pragma unroll
        for (int j = 0; j < 8; ++j) {
            float2 r;
            r.x = hadd(acc[j][0]) + bv.x;
            r.y = hadd(acc[j][1]) + bv.y;
            *(float2*)(sO + (m0 + j) * 128 + n0) = r;
        }
    }
    __syncthreads();

    // ---- residual + LN2 + mask: warp ty handles rows ty, ty+8, ty+16, ty+24 ----
    #pragma unroll
    for (int rr = 0; rr < 4; ++rr) {
        int r = ty + rr * 8;
        float v[4];
        float s = 0.f, s2 = 0.f;
        #pragma unroll
        for (int i = 0; i < 4; ++i) {
            int n = tx + i * 32;
            v[i] = sH[r * 128 + n] + sO[r * 128 + n];
            s += v[i]; s2 += v[i] * v[i];
        }
        #pragma unroll
        for (int off = 16; off > 0; off >>= 1) {
            s  += __shfl_xor_sync(0xffffffffu, s,  off);
            s2 += __shfl_xor_sync(0xffffffffu, s2, off);
        }
        float mean = s * (1.0f / 128.0f);
        float rstd = rsqrtf(s2 * (1.0f / 128.0f) - mean * mean + 1e-5f);
        float mv = mask_V[nb + r];
        #pragma unroll
        for (int i = 0; i < 4; ++i) {
            int n = tx + i * 32;
            out[(size_t)(nb + r) * Hdim + n] =
                mv * ((v[i] - mean) * rstd * ln2_g[n] + ln2_b[n]);
        }
    }
}

extern "C" void kernel_launch(void* const* d_in, const int* in_sizes, int n_in,
                              void* d_out, int out_size) {
    const float* h_V         = (const float*)d_in[0];
    const float* h_E         = (const float*)d_in[1];
    const float* mask_V      = (const float*)d_in[2];
    const float* mask_attend = (const float*)d_in[3];
    const float* W1_w        = (const float*)d_in[4];
    const float* W1_b        = (const float*)d_in[5];
    const float* W2_w        = (const float*)d_in[6];
    const float* W2_b        = (const float*)d_in[7];
    const float* W3_w        = (const float*)d_in[8];
    const float* W3_b        = (const float*)d_in[9];
    const float* ln1_g       = (const float*)d_in[10];
    const float* ln1_b       = (const float*)d_in[11];
    const float* ln2_g       = (const float*)d_in[12];
    const float* ln2_b       = (const float*)d_in[13];
    const float* Win_w       = (const float*)d_in[14];
    const float* Win_b       = (const float*)d_in[15];
    const float* Wout_w      = (const float*)d_in[16];
    const float* Wout_b      = (const float*)d_in[17];

    int nodes = in_sizes[0] / Hdim;   // 4096

    prep_weights<<<448, 256>>>(W1_w, W2_w, W3_w, Win_w, Wout_w);

    cudaFuncSetAttribute(edge_mlp_kernel,
                         cudaFuncAttributeMaxDynamicSharedMemorySize, SM1_BYTES);
    cudaFuncSetAttribute(ffn_kernel,
                         cudaFuncAttributeMaxDynamicSharedMemorySize, SM2_BYTES);

    edge_mlp_kernel<<<nodes, NT, SM1_BYTES>>>(
        h_V, h_E, mask_attend, W1_b, W2_b, W3_b, ln1_g, ln1_b);

    ffn_kernel<<<nodes / 32, NT, SM2_BYTES>>>(
        mask_V, Win_b, Wout_b, ln2_g, ln2_b, (float*)d_out);
}

// round 9
// speedup vs baseline: 1.8878x; 1.0002x over previous
#include <cuda_runtime.h>
#include <math.h>

#define Hdim   128
#define NINdim 384
#define CIN    512
#define KNB    48
#define FFdim  512
#define NT     256

typedef unsigned long long u64;

// ---------------- pre-paired weights (prep kernel output) ----------------
// Wp[k2][n] = (W[n][2k2], W[n][2k2+1])  -- k-pair interleaved, n contiguous
__device__ float2 g_W1p[256 * 128];
__device__ float2 g_W2p[64 * 128];
__device__ float2 g_W3p[64 * 128];
__device__ float2 g_Winp[64 * 512];    // [k2][f]
__device__ float2 g_Woutp[256 * 128];  // [k2][n]
__device__ float  g_Hbuf[4096 * 128];  // post-LN1 hidden

__global__ void prep_weights(const float* __restrict__ W1_w,
                             const float* __restrict__ W2_w,
                             const float* __restrict__ W3_w,
                             const float* __restrict__ Win_w,
                             const float* __restrict__ Wout_w) {
    int idx = blockIdx.x * blockDim.x + threadIdx.x;
    if (idx < 32768) {                         // W1p: k2<256, n<128
        int k2 = idx >> 7, n = idx & 127;
        g_W1p[idx] = make_float2(W1_w[n * 512 + 2 * k2], W1_w[n * 512 + 2 * k2 + 1]);
    } else if (idx < 40960) {                  // W2p: k2<64
        int i = idx - 32768;
        int k2 = i >> 7, n = i & 127;
        g_W2p[i] = make_float2(W2_w[n * 128 + 2 * k2], W2_w[n * 128 + 2 * k2 + 1]);
    } else if (idx < 49152) {                  // W3p
        int i = idx - 40960;
        int k2 = i >> 7, n = i & 127;
        g_W3p[i] = make_float2(W3_w[n * 128 + 2 * k2], W3_w[n * 128 + 2 * k2 + 1]);
    } else if (idx < 81920) {                  // Winp: k2<64, f<512
        int i = idx - 49152;
        int k2 = i >> 9, f = i & 511;
        g_Winp[i] = make_float2(Win_w[f * 128 + 2 * k2], Win_w[f * 128 + 2 * k2 + 1]);
    } else if (idx < 114688) {                 // Woutp: k2<256, n<128
        int i = idx - 81920;
        int k2 = i >> 7, n = i & 127;
        g_Woutp[i] = make_float2(Wout_w[n * 512 + 2 * k2], Wout_w[n * 512 + 2 * k2 + 1]);
    }
}

// ---------------- kernel-1 shared layout (floats) ----------------
#define OFF_A   0        // X k-tile [48][128] in B; Y2 in C-out/D     6144
#define OFF_Y1  6144     // Y1 [48][128]                               6144
#define T_RED   12288    // [4][128]
#define T_VEC   12800
#define T_ST    12928
#define SM1_FLOATS 12936
#define SM1_BYTES  (SM1_FLOATS * 4)     // ~52 KB

// ---------------- kernel-2 shared layout ----------------
#define K2_H   0         // H [32][128]            4096
#define K2_F   4096      // F [32][512]           16384
#define K2_O   20480     // O [32][128]            4096
#define SM2_FLOATS 24576
#define SM2_BYTES  (SM2_FLOATS * 4)

__device__ __forceinline__ float gelu_erf(float x) {
    return 0.5f * x * (1.0f + erff(x * 0.70710678118654752440f));
}
__device__ __forceinline__ void fma2(u64& d, u64 a, u64 b) {
    asm("fma.rn.f32x2 %0, %1, %2, %0;" : "+l"(d) : "l"(a), "l"(b));
}
__device__ __forceinline__ void lds2(u64& a, u64& b, unsigned addr) {
    asm volatile("ld.shared.v2.b64 {%0,%1}, [%2];" : "=l"(a), "=l"(b) : "r"(addr));
}
__device__ __forceinline__ float hadd(u64 p) {
    float lo, hi;
    asm("mov.b64 {%0,%1}, %2;" : "=f"(lo), "=f"(hi) : "l"(p));
    return lo + hi;
}

__device__ __forceinline__ void ln_stats(const float* v, float* sStats, int o, int tid) {
    if (tid < 32) {
        float s = 0.f, s2 = 0.f;
        #pragma unroll
        for (int i = 0; i < 4; ++i) {
            float x = v[tid + i * 32];
            s += x; s2 += x * x;
        }
        #pragma unroll
        for (int off = 16; off > 0; off >>= 1) {
            s  += __shfl_xor_sync(0xffffffffu, s,  off);
            s2 += __shfl_xor_sync(0xffffffffu, s2, off);
        }
        if (tid == 0) {
            float mean = s * (1.0f / 128.0f);
            float var  = s2 * (1.0f / 128.0f) - mean * mean;
            sStats[o]     = mean;
            sStats[o + 1] = rsqrtf(var + 1e-5f);
        }
    }
}

// One 2-k2 step (4 k). Weights direct from global (L1-resident tile).
// WP: float* at this lane's (k2, n0); WROWF: floats per k2 row.
#define INNERG(J, XB, XSTRIDE, WP, WROWF)                              \
  {                                                                    \
    ulonglong2 va = __ldg((const ulonglong2*)(WP));                    \
    ulonglong2 vb = __ldg((const ulonglong2*)((WP) + (WROWF)));        \
    _Pragma("unroll")                                                  \
    for (int j = 0; j < (J); ++j) {                                    \
      u64 xa, xb; lds2(xa, xb, (XB) + j * (XSTRIDE));                  \
      fma2(acc[j][0], xa, va.x); fma2(acc[j][1], xa, va.y);            \
      fma2(acc[j][0], xb, vb.x); fma2(acc[j][1], xb, vb.y);            \
    }                                                                  \
  }

// =========================================================================
// Kernel 1: per node — edge MLP (3 layers), masked aggregate, LN1 -> g_Hbuf
// Warps: (wm 0..3) x (wn 0..1); warp tile 12 m x 64 n. Weights via __ldg.
// =========================================================================
__global__ void __launch_bounds__(NT, 2)
edge_mlp_kernel(
    const float* __restrict__ h_V, const float* __restrict__ h_E,
    const float* __restrict__ mask_attend,
    const float* __restrict__ W1_b, const float* __restrict__ W2_b,
    const float* __restrict__ W3_b,
    const float* __restrict__ ln1_g, const float* __restrict__ ln1_b)
{
    extern __shared__ float sm[];
    const int tid = threadIdx.x;
    const int tx  = tid & 31;
    const int ty  = tid >> 5;
    const int wm  = ty >> 1;            // 0..3 -> m block of 12
    const int wn  = ty & 1;             // 0..1 -> n block of 64
    const int m0  = wm * 12;
    const int n0  = wn * 64 + 2 * tx;   // lane's first n
    const int ng  = blockIdx.x;

    const unsigned sbase = (unsigned)__cvta_generic_to_shared(sm);
    float* sA  = sm + OFF_A;
    float* sY1 = sm + OFF_Y1;

    u64 acc[12][2];
    const unsigned xbA = sbase + OFF_A * 4 + m0 * 512;
    const unsigned xbY = sbase + OFF_Y1 * 4 + m0 * 512;

    const float* gW1 = (const float*)g_W1p + 2 * n0;   // + k2*256
    const float* gW2 = (const float*)g_W2p + 2 * n0;
    const float* gW3 = (const float*)g_W3p + 2 * n0;

    const float4* hv4 = (const float4*)(h_V + (size_t)ng * Hdim);
    const float4* he4 = (const float4*)(h_E + (size_t)ng * (KNB * NINdim));

    // ================= Phase B: Y1 = gelu(X @ W1^T + b1), k-tiled x4 =================
    #pragma unroll
    for (int j = 0; j < 12; ++j) { acc[j][0] = 0ULL; acc[j][1] = 0ULL; }

    for (int kt = 0; kt < 4; ++kt) {
        __syncthreads();
        #pragma unroll
        for (int it = 0; it < 6; ++it) {
            int idx = it * NT + tid;
            int m = idx >> 5, q = idx & 31;
            ((float4*)sA)[m * 32 + q] =
                (kt == 0) ? hv4[q] : he4[m * 96 + (kt - 1) * 32 + q];
        }
        __syncthreads();
        const float* wp = gW1 + kt * 16384;
        #pragma unroll 4
        for (int it = 0; it < 32; ++it)
            INNERG(12, xbA + it * 16, 512, wp + it * 512, 256);
    }
    {
        float2 bv = *(const float2*)(W1_b + n0);
        #pragma unroll
        for (int j = 0; j < 12; ++j) {
            float2 r;
            r.x = gelu_erf(hadd(acc[j][0]) + bv.x);
            r.y = gelu_erf(hadd(acc[j][1]) + bv.y);
            *(float2*)(sY1 + (m0 + j) * 128 + n0) = r;
            acc[j][0] = 0ULL; acc[j][1] = 0ULL;
        }
    }
    __syncthreads();

    // ================= Phase C: Y2 = gelu(Y1 @ W2^T + b2) =================
    #pragma unroll 4
    for (int it = 0; it < 32; ++it)
        INNERG(12, xbY + it * 16, 512, gW2 + it * 512, 256);
    {
        float2 bv = *(const float2*)(W2_b + n0);
        #pragma unroll
        for (int j = 0; j < 12; ++j) {
            float2 r;
            r.x = gelu_erf(hadd(acc[j][0]) + bv.x);
            r.y = gelu_erf(hadd(acc[j][1]) + bv.y);
            *(float2*)(sA + (m0 + j) * 128 + n0) = r;
            acc[j][0] = 0ULL; acc[j][1] = 0ULL;
        }
    }
    __syncthreads();

    // ================= Phase D: msg = Y2 @ W3^T + b3, masked sum =================
    #pragma unroll 4
    for (int it = 0; it < 32; ++it)
        INNERG(12, xbA + it * 16, 512, gW3 + it * 512, 256);

    float* sRed = sm + T_RED;     // [4][128] per-wm partials
    {
        float2 bv = *(const float2*)(W3_b + n0);
        float p0 = 0.f, p1 = 0.f;
        #pragma unroll
        for (int j = 0; j < 12; ++j) {
            float ma = mask_attend[(size_t)ng * KNB + m0 + j];
            p0 = fmaf(ma, hadd(acc[j][0]) + bv.x, p0);
            p1 = fmaf(ma, hadd(acc[j][1]) + bv.y, p1);
        }
        *(float2*)(sRed + wm * 128 + n0) = make_float2(p0, p1);
    }
    __syncthreads();

    float* sVec   = sm + T_VEC;
    float* sStats = sm + T_ST;
    if (tid < 128) {
        float dh = sRed[tid] + sRed[128 + tid] + sRed[256 + tid] + sRed[384 + tid];
        dh *= (1.0f / 30.0f);
        sVec[tid] = h_V[(size_t)ng * Hdim + tid] + dh;
    }
    __syncthreads();
    ln_stats(sVec, sStats, 0, tid);
    __syncthreads();
    if (tid < 128) {
        g_Hbuf[(size_t)ng * Hdim + tid] =
            (sVec[tid] - sStats[0]) * sStats[1] * ln1_g[tid] + ln1_b[tid];
    }
}

// =========================================================================
// Kernel 2: batched FFN + LN2 + mask (32 nodes per CTA)
// Warps: (wm 0..3) x (wn 0..1); warp tile 8 m x 64 n. Weights via __ldg.
// =========================================================================
__global__ void __launch_bounds__(NT, 1)
ffn_kernel(const float* __restrict__ mask_V,
           const float* __restrict__ Win_b, const float* __restrict__ Wout_b,
           const float* __restrict__ ln2_g, const float* __restrict__ ln2_b,
           float* __restrict__ out)
{
    extern __shared__ float sm[];
    const int tid = threadIdx.x;
    const int tx  = tid & 31;
    const int ty  = tid >> 5;
    const int wm  = ty >> 1;
    const int wn  = ty & 1;
    const int m0  = wm * 8;
    const int n0  = wn * 64 + 2 * tx;
    const int nb  = blockIdx.x * 32;

    const unsigned sbase = (unsigned)__cvta_generic_to_shared(sm);
    float* sH = sm + K2_H;
    float* sF = sm + K2_F;
    float* sO = sm + K2_O;

    const float* gWin  = (const float*)g_Winp;    // [k2][512] pairs
    const float* gWout = (const float*)g_Woutp + 2 * n0;

    // stage H [32][128]
    {
        const float4* src = (const float4*)(g_Hbuf + (size_t)nb * Hdim);
        float4* dst = (float4*)sH;
        #pragma unroll
        for (int i = 0; i < 4; ++i) dst[i * NT + tid] = src[i * NT + tid];
    }
    __syncthreads();

    u64 acc[8][2];

    // ---- GEMM1: F = gelu(H @ Win^T + bin), n-blocked over 512 ----
    for (int nblk = 0; nblk < 4; ++nblk) {
        #pragma unroll
        for (int j = 0; j < 8; ++j) { acc[j][0] = 0ULL; acc[j][1] = 0ULL; }
        {
            const unsigned xrow = sbase + K2_H * 4 + m0 * 512;
            const float* wp = gWin + nblk * 256 + 2 * n0;   // f = nblk*128 + n0
            #pragma unroll 4
            for (int it = 0; it < 32; ++it)
                INNERG(8, xrow + it * 16, 512, wp + it * 2048, 1024);
        }
        float2 bv = *(const float2*)(Win_b + nblk * 128 + n0);
        #pragma unroll
        for (int j = 0; j < 8; ++j) {
            float2 r;
            r.x = gelu_erf(hadd(acc[j][0]) + bv.x);
            r.y = gelu_erf(hadd(acc[j][1]) + bv.y);
            *(float2*)(sF + (m0 + j) * 512 + nblk * 128 + n0) = r;
        }
    }
    __syncthreads();

    // ---- GEMM2: O = F @ Wout^T + bout ----
    #pragma unroll
    for (int j = 0; j < 8; ++j) { acc[j][0] = 0ULL; acc[j][1] = 0ULL; }
    for (int kt = 0; kt < 4; ++kt) {
        const unsigned xrow = sbase + K2_F * 4 + m0 * 2048;
        const float* wp = gWout + kt * 16384;
        #pragma unroll 4
        for (int it = 0; it < 32; ++it)
            INNERG(8, xrow + kt * 512 + it * 16, 2048, wp + it * 512, 256);
    }
    {
        float2 bv = *(const float2*)(Wout_b + n0);
        #pragma unroll
        for (int j = 0; j < 8; ++j) {
            float2 r;
            r.x = hadd(acc[j][0]) + bv.x;
            r.y = hadd(acc[j][1]) + bv.y;
            *(float2*)(sO + (m0 + j) * 128 + n0) = r;
        }
    }
    __syncthreads();

    // ---- residual + LN2 + mask: warp ty handles rows ty, ty+8, ty+16, ty+24 ----
    #pragma unroll
    for (int rr = 0; rr < 4; ++rr) {
        int r = ty + rr * 8;
        float v[4];
        float s = 0.f, s2 = 0.f;
        #pragma unroll
        for (int i = 0; i < 4; ++i) {
            int n = tx + i * 32;
            v[i] = sH[r * 128 + n] + sO[r * 128 + n];
            s += v[i]; s2 += v[i] * v[i];
        }
        #pragma unroll
        for (int off = 16; off > 0; off >>= 1) {
            s  += __shfl_xor_sync(0xffffffffu, s,  off);
            s2 += __shfl_xor_sync(0xffffffffu, s2, off);
        }
        float mean = s * (1.0f / 128.0f);
        float rstd = rsqrtf(s2 * (1.0f / 128.0f) - mean * mean + 1e-5f);
        float mv = mask_V[nb + r];
        #pragma unroll
        for (int i = 0; i < 4; ++i) {
            int n = tx + i * 32;
            out[(size_t)(nb + r) * Hdim + n] =
                mv * ((v[i] - mean) * rstd * ln2_g[n] + ln2_b[n]);
        }
    }
}

extern "C" void kernel_launch(void* const* d_in, const int* in_sizes, int n_in,
                              void* d_out, int out_size) {
    const float* h_V         = (const float*)d_in[0];
    const float* h_E         = (const float*)d_in[1];
    const float* mask_V      = (const float*)d_in[2];
    const float* mask_attend = (const float*)d_in[3];
    const float* W1_w        = (const float*)d_in[4];
    const float* W1_b        = (const float*)d_in[5];
    const float* W2_w        = (const float*)d_in[6];
    const float* W2_b        = (const float*)d_in[7];
    const float* W3_w        = (const float*)d_in[8];
    const float* W3_b        = (const float*)d_in[9];
    const float* ln1_g       = (const float*)d_in[10];
    const float* ln1_b       = (const float*)d_in[11];
    const float* ln2_g       = (const float*)d_in[12];
    const float* ln2_b       = (const float*)d_in[13];
    const float* Win_w       = (const float*)d_in[14];
    const float* Win_b       = (const float*)d_in[15];
    const float* Wout_w      = (const float*)d_in[16];
    const float* Wout_b      = (const float*)d_in[17];

    int nodes = in_sizes[0] / Hdim;   // 4096

    prep_weights<<<448, 256>>>(W1_w, W2_w, W3_w, Win_w, Wout_w);

    cudaFuncSetAttribute(edge_mlp_kernel,
                         cudaFuncAttributeMaxDynamicSharedMemorySize, SM1_BYTES);
    cudaFuncSetAttribute(ffn_kernel,
                         cudaFuncAttributeMaxDynamicSharedMemorySize, SM2_BYTES);

    edge_mlp_kernel<<<nodes, NT, SM1_BYTES>>>(
        h_V, h_E, mask_attend, W1_b, W2_b, W3_b, ln1_g, ln1_b);

    ffn_kernel<<<nodes / 32, NT, SM2_BYTES>>>(
        mask_V, Win_b, Wout_b, ln2_g, ln2_b, (float*)d_out);
}

// round 11
// speedup vs baseline: 2.6578x; 1.4079x over previous
#include <cuda_runtime.h>
#include <cuda_bf16.h>
#include <math.h>

#define Hdim 128
#define KNB  48
#define NT   256
typedef unsigned long long u64;

__device__ __nv_bfloat16 g_W1bh[128 * 384];   // [n][k] hi
__device__ __nv_bfloat16 g_W1bl[128 * 384];
__device__ __nv_bfloat16 g_W2h[128 * 128];
__device__ __nv_bfloat16 g_W2l[128 * 128];
__device__ __nv_bfloat16 g_W3h[128 * 128];
__device__ __nv_bfloat16 g_W3l[128 * 128];
__device__ float2 g_Winp[64 * 512];
__device__ float2 g_Woutp[256 * 128];
__device__ float  g_hvc[4096 * 128];
__device__ float  g_dh[4096 * 128];
__device__ float  g_Hbuf[4096 * 128];

__device__ __forceinline__ float gelu_erf(float x) {
    return 0.5f * x * (1.0f + erff(x * 0.70710678118654752440f));
}
__device__ __forceinline__ void fma2(u64& d, u64 a, u64 b) {
    asm("fma.rn.f32x2 %0, %1, %2, %0;" : "+l"(d) : "l"(a), "l"(b));
}
__device__ __forceinline__ void lds2(u64& a, u64& b, unsigned addr) {
    asm volatile("ld.shared.v2.b64 {%0,%1}, [%2];" : "=l"(a), "=l"(b) : "r"(addr));
}
__device__ __forceinline__ float hadd(u64 p) {
    float lo, hi;
    asm("mov.b64 {%0,%1}, %2;" : "=f"(lo), "=f"(hi) : "l"(p));
    return lo + hi;
}
__device__ __forceinline__ unsigned pack2(__nv_bfloat16 a, __nv_bfloat16 b) {
    return ((unsigned)__bfloat16_as_ushort(b) << 16) | (unsigned)__bfloat16_as_ushort(a);
}
__device__ __forceinline__ void bsplit(float x, __nv_bfloat16& h, __nv_bfloat16& l) {
    h = __float2bfloat16_rn(x);
    l = __float2bfloat16_rn(x - __bfloat162float(h));
}
// mma.sync m16n8k16 bf16 -> f32, C += A*B
__device__ __forceinline__ void mma16816(float* c, const unsigned* a, const unsigned* b) {
    asm volatile(
        "mma.sync.aligned.m16n8k16.row.col.f32.bf16.bf16.f32 "
        "{%0,%1,%2,%3}, {%4,%5,%6,%7}, {%8,%9}, {%0,%1,%2,%3};"
        : "+f"(c[0]), "+f"(c[1]), "+f"(c[2]), "+f"(c[3])
        : "r"(a[0]), "r"(a[1]), "r"(a[2]), "r"(a[3]), "r"(b[0]), "r"(b[1]));
}

__global__ void prep_weights(const float* __restrict__ W1_w, const float* __restrict__ W2_w,
                             const float* __restrict__ W3_w, const float* __restrict__ Win_w,
                             const float* __restrict__ Wout_w) {
    int idx = blockIdx.x * blockDim.x + threadIdx.x;
    __nv_bfloat16 h, l;
    if (idx < 49152) {
        int n = idx / 384, k = idx % 384;
        bsplit(W1_w[n * 512 + 128 + k], h, l);
        g_W1bh[idx] = h; g_W1bl[idx] = l;
    } else if (idx < 65536) {
        int i = idx - 49152;
        bsplit(W2_w[i], h, l);
        g_W2h[i] = h; g_W2l[i] = l;
    } else if (idx < 81920) {
        int i = idx - 65536;
        bsplit(W3_w[i], h, l);
        g_W3h[i] = h; g_W3l[i] = l;
    } else if (idx < 114688) {
        int i = idx - 81920;
        int k2 = i >> 9, f = i & 511;
        g_Winp[i] = make_float2(Win_w[f * 128 + 2 * k2], Win_w[f * 128 + 2 * k2 + 1]);
    } else if (idx < 147456) {
        int i = idx - 114688;
        int k2 = i >> 7, n = i & 127;
        g_Woutp[i] = make_float2(Wout_w[n * 512 + 2 * k2], Wout_w[n * 512 + 2 * k2 + 1]);
    }
}

// hvc = h_V @ W1a^T + b1 (exact fp32); also zero g_dh
__global__ void __launch_bounds__(NT, 1)
hvc_kernel(const float* __restrict__ h_V, const float* __restrict__ W1_w,
           const float* __restrict__ W1_b) {
    extern __shared__ float smh[];
    float* sW  = smh;            // [k][n]
    float* sHv = smh + 16384;    // 8 x 128
    const int tid = threadIdx.x;
    const int nb  = blockIdx.x * 8;
    #pragma unroll
    for (int i = 0; i < 16; ++i) {
        int id4 = i * NT + tid;
        int k4 = id4 >> 7, n = id4 & 127;
        float4 v = ((const float4*)(W1_w + (size_t)n * 512))[k4];
        sW[(4 * k4 + 0) * 128 + n] = v.x;
        sW[(4 * k4 + 1) * 128 + n] = v.y;
        sW[(4 * k4 + 2) * 128 + n] = v.z;
        sW[(4 * k4 + 3) * 128 + n] = v.w;
    }
    {
        int node = tid >> 5, q = tid & 31;
        float4 v = ((const float4*)(h_V + (size_t)(nb + node) * 128))[q];
        *(float4*)(sHv + node * 128 + 4 * q) = v;
        ((float4*)(g_dh + (size_t)nb * 128))[tid] = make_float4(0.f, 0.f, 0.f, 0.f);
    }
    __syncthreads();
    #pragma unroll
    for (int it = 0; it < 4; ++it) {
        int o = it * NT + tid;
        int node = o >> 7, col = o & 127;
        const float* hv = sHv + node * 128;
        float a = W1_b[col];
        #pragma unroll 8
        for (int k = 0; k < 128; ++k) a = fmaf(hv[k], sW[k * 128 + col], a);
        g_hvc[(size_t)(nb + node) * 128 + col] = a;
    }
}

// ---- edge GEMM smem layout (byte offsets); chunk = [128 rows][33 b32] = 16896B ----
#define CHB     16896
#define SM_BIAS 0
#define SM_HVC  1024
#define SM_Y1   3072                    // 4 chunks (c0h,c0l,c1h,c1l)
#define SM_X    (SM_Y1 + 4 * CHB)       // GEMM1 A stage (h,l); later Y2 (4 chunks)
#define SM_B    (SM_X + 4 * CHB)        // B stage (h,l)
#define SM_TOT  (SM_B + 2 * CHB)        // 172032

// stage one 64k chunk of B weights [128n][64k] hi/lo from prepped bf16 [n][K]
__device__ __forceinline__ void stage_B(char* smem, const __nv_bfloat16* gh,
                                        const __nv_bfloat16* gl, int K, int c, int tid) {
    unsigned* dh = (unsigned*)(smem + SM_B);
    unsigned* dl = dh + CHB / 4;
    #pragma unroll
    for (int i = 0; i < 4; ++i) {
        int idx = i * NT + tid;          // 0..1023
        int n = idx >> 3, q = idx & 7;
        uint4 vh = *(const uint4*)(gh + (size_t)n * K + c * 64 + q * 8);
        uint4 vl = *(const uint4*)(gl + (size_t)n * K + c * 64 + q * 8);
        int o = n * 33 + q * 4;
        dh[o] = vh.x; dh[o + 1] = vh.y; dh[o + 2] = vh.z; dh[o + 3] = vh.w;
        dl[o] = vl.x; dl[o + 1] = vl.y; dl[o + 2] = vl.z; dl[o + 3] = vl.w;
    }
}

// compute one 64k chunk: acc[64] += A(128x64) * B^T, split-bf16 (hh+hl+lh)
__device__ __forceinline__ void chunk_mma(const unsigned* pAh, const unsigned* pAl,
                                          const unsigned* pBh, const unsigned* pBl,
                                          float* acc, int m0, int nb0, int g, int t4) {
    #pragma unroll
    for (int s = 0; s < 4; ++s) {
        unsigned ah[2][4], al[2][4];
        #pragma unroll
        for (int t = 0; t < 2; ++t) {
            int r = (m0 + t * 16 + g) * 33 + s * 8 + t4;
            ah[t][0] = pAh[r];           ah[t][1] = pAh[r + 8 * 33];
            ah[t][2] = pAh[r + 4];       ah[t][3] = pAh[r + 8 * 33 + 4];
            al[t][0] = pAl[r];           al[t][1] = pAl[r + 8 * 33];
            al[t][2] = pAl[r + 4];       al[t][3] = pAl[r + 8 * 33 + 4];
        }
        #pragma unroll
        for (int u = 0; u < 8; ++u) {
            int o = (nb0 + u * 8 + g) * 33 + s * 8 + t4;
            unsigned bh[2] = { pBh[o], pBh[o + 4] };
            unsigned bl[2] = { pBl[o], pBl[o + 4] };
            #pragma unroll
            for (int t = 0; t < 2; ++t) {
                float* cc = acc + (t * 8 + u) * 4;
                mma16816(cc, ah[t], bh);
                mma16816(cc, ah[t], bl);
                mma16816(cc, al[t], bh);
            }
        }
    }
}

__global__ void __launch_bounds__(NT, 1)
edge_gemm_kernel(const float* __restrict__ h_E, const float* __restrict__ mask_attend,
                 const float* __restrict__ W2_b, const float* __restrict__ W3_b,
                 int n_nodes) {
    extern __shared__ char smem[];
    const int tid = threadIdx.x;
    const int wid = tid >> 5;
    const int lane = tid & 31;
    const int g = lane >> 2, t4 = lane & 3;
    const int wm = wid >> 1, wn = wid & 1;
    const int m0 = wm * 32, nb0 = wn * 64;
    const int base = blockIdx.x * 128;
    const int n0 = base / 48;

    if (tid < 128) {
        ((float*)(smem + SM_BIAS))[tid]       = W2_b[tid];
        ((float*)(smem + SM_BIAS))[128 + tid] = W3_b[tid];
    }
    for (int t = tid; t < 512; t += NT) {
        int gg = t >> 7, c = t & 127;
        int nd = n0 + gg;
        ((float*)(smem + SM_HVC))[t] = (nd < n_nodes) ? g_hvc[(size_t)nd * 128 + c] : 0.f;
    }

    float acc[64];
    #pragma unroll
    for (int i = 0; i < 64; ++i) acc[i] = 0.f;

    // ---------- GEMM1: h_E @ W1b^T, K=384 ----------
    for (int c = 0; c < 6; ++c) {
        __syncthreads();
        // stage A chunk from h_E (fp32 -> bf16 hi/lo)
        {
            unsigned* dh = (unsigned*)(smem + SM_X);
            unsigned* dl = dh + CHB / 4;
            #pragma unroll
            for (int i = 0; i < 4; ++i) {
                int idx = i * NT + tid;
                int r = idx >> 3, q = idx & 7;
                const float4* p = (const float4*)(h_E + (size_t)(base + r) * 384 + c * 64 + q * 8);
                float4 v0 = p[0], v1 = p[1];
                float f[8] = {v0.x, v0.y, v0.z, v0.w, v1.x, v1.y, v1.z, v1.w};
                __nv_bfloat16 hb[8], lb[8];
                #pragma unroll
                for (int j = 0; j < 8; ++j) bsplit(f[j], hb[j], lb[j]);
                int o = r * 33 + q * 4;
                dh[o]     = pack2(hb[0], hb[1]); dh[o + 1] = pack2(hb[2], hb[3]);
                dh[o + 2] = pack2(hb[4], hb[5]); dh[o + 3] = pack2(hb[6], hb[7]);
                dl[o]     = pack2(lb[0], lb[1]); dl[o + 1] = pack2(lb[2], lb[3]);
                dl[o + 2] = pack2(lb[4], lb[5]); dl[o + 3] = pack2(lb[6], lb[7]);
            }
        }
        stage_B(smem, g_W1bh, g_W1bl, 384, c, tid);
        __syncthreads();
        chunk_mma((unsigned*)(smem + SM_X), (unsigned*)(smem + SM_X) + CHB / 4,
                  (unsigned*)(smem + SM_B), (unsigned*)(smem + SM_B) + CHB / 4,
                  acc, m0, nb0, g, t4);
    }
    __syncthreads();
    // epilogue 1: y1 = gelu(D + hvc[node]) -> Y1 chunks (bf16 hi/lo)
    {
        const float* hvc = (const float*)(smem + SM_HVC);
        unsigned* y = (unsigned*)(smem + SM_Y1);
        #pragma unroll
        for (int t = 0; t < 2; ++t) {
            int r1 = m0 + t * 16 + g, r2 = r1 + 8;
            int h1 = (base + r1) / 48 - n0, h2 = (base + r2) / 48 - n0;
            #pragma unroll
            for (int u = 0; u < 8; ++u) {
                int n = nb0 + u * 8 + 2 * t4;
                const float* cc = acc + (t * 8 + u) * 4;
                float ya = gelu_erf(cc[0] + hvc[h1 * 128 + n]);
                float yb = gelu_erf(cc[1] + hvc[h1 * 128 + n + 1]);
                float yc = gelu_erf(cc[2] + hvc[h2 * 128 + n]);
                float yd = gelu_erf(cc[3] + hvc[h2 * 128 + n + 1]);
                __nv_bfloat16 ha, la, hb, lb, hc, lc, hd, ld;
                bsplit(ya, ha, la); bsplit(yb, hb, lb);
                bsplit(yc, hc, lc); bsplit(yd, hd, ld);
                int ch = n >> 6, col = (n & 63) >> 1;
                unsigned* yh = y + (2 * ch) * (CHB / 4);
                unsigned* yl = y + (2 * ch + 1) * (CHB / 4);
                yh[r1 * 33 + col] = pack2(ha, hb);
                yl[r1 * 33 + col] = pack2(la, lb);
                yh[r2 * 33 + col] = pack2(hc, hd);
                yl[r2 * 33 + col] = pack2(lc, ld);
            }
        }
    }
    #pragma unroll
    for (int i = 0; i < 64; ++i) acc[i] = 0.f;
    __syncthreads();

    // ---------- GEMM2: Y1 @ W2^T, K=128 ----------
    for (int c = 0; c < 2; ++c) {
        stage_B(smem, g_W2h, g_W2l, 128, c, tid);
        __syncthreads();
        chunk_mma((unsigned*)(smem + SM_Y1) + (2 * c) * (CHB / 4),
                  (unsigned*)(smem + SM_Y1) + (2 * c + 1) * (CHB / 4),
                  (unsigned*)(smem + SM_B), (unsigned*)(smem + SM_B) + CHB / 4,
                  acc, m0, nb0, g, t4);
        __syncthreads();
    }
    // epilogue 2: y2 = gelu(D + b2) -> X region chunks
    {
        const float* b2 = (const float*)(smem + SM_BIAS);
        unsigned* y = (unsigned*)(smem + SM_X);
        #pragma unroll
        for (int t = 0; t < 2; ++t) {
            int r1 = m0 + t * 16 + g, r2 = r1 + 8;
            #pragma unroll
            for (int u = 0; u < 8; ++u) {
                int n = nb0 + u * 8 + 2 * t4;
                const float* cc = acc + (t * 8 + u) * 4;
                float ya = gelu_erf(cc[0] + b2[n]);
                float yb = gelu_erf(cc[1] + b2[n + 1]);
                float yc = gelu_erf(cc[2] + b2[n]);
                float yd = gelu_erf(cc[3] + b2[n + 1]);
                __nv_bfloat16 ha, la, hb, lb, hc, lc, hd, ld;
                bsplit(ya, ha, la); bsplit(yb, hb, lb);
                bsplit(yc, hc, lc); bsplit(yd, hd, ld);
                int ch = n >> 6, col = (n & 63) >> 1;
                unsigned* yh = y + (2 * ch) * (CHB / 4);
                unsigned* yl = y + (2 * ch + 1) * (CHB / 4);
                yh[r1 * 33 + col] = pack2(ha, hb);
                yl[r1 * 33 + col] = pack2(la, lb);
                yh[r2 * 33 + col] = pack2(hc, hd);
                yl[r2 * 33 + col] = pack2(lc, ld);
            }
        }
    }
    #pragma unroll
    for (int i = 0; i < 64; ++i) acc[i] = 0.f;
    __syncthreads();

    // ---------- GEMM3: Y2 @ W3^T, K=128 ----------
    for (int c = 0; c < 2; ++c) {
        stage_B(smem, g_W3h, g_W3l, 128, c, tid);
        __syncthreads();
        chunk_mma((unsigned*)(smem + SM_X) + (2 * c) * (CHB / 4),
                  (unsigned*)(smem + SM_X) + (2 * c + 1) * (CHB / 4),
                  (unsigned*)(smem + SM_B), (unsigned*)(smem + SM_B) + CHB / 4,
                  acc, m0, nb0, g, t4);
        __syncthreads();
    }
    // epilogue 3: msg = (D + b3) * mask -> sMsg [n][129]; segment sums -> g_dh
    {
        const float* b3 = (const float*)(smem + SM_BIAS) + 128;
        float* sMsg = (float*)(smem + SM_Y1);
        #pragma unroll
        for (int t = 0; t < 2; ++t) {
            int r1 = m0 + t * 16 + g, r2 = r1 + 8;
            float mk1 = mask_attend[base + r1];
            float mk2 = mask_attend[base + r2];
            #pragma unroll
            for (int u = 0; u < 8; ++u) {
                int n = nb0 + u * 8 + 2 * t4;
                const float* cc = acc + (t * 8 + u) * 4;
                sMsg[n * 129 + r1]       = (cc[0] + b3[n])     * mk1;
                sMsg[(n + 1) * 129 + r1] = (cc[1] + b3[n + 1]) * mk1;
                sMsg[n * 129 + r2]       = (cc[2] + b3[n])     * mk2;
                sMsg[(n + 1) * 129 + r2] = (cc[3] + b3[n + 1]) * mk2;
            }
        }
    }
    __syncthreads();
    if (tid < 128) {
        const float* sMsg = (const float*)(smem + SM_Y1);
        int col = tid;
        #pragma unroll
        for (int gg = 0; gg < 4; ++gg) {
            int ng = n0 + gg;
            if (ng >= n_nodes) break;
            int lo = ng * 48 - base, hi = lo + 48;
            if (lo < 0) lo = 0;
            if (hi > 128) hi = 128;
            if (lo < hi) {
                float s = 0.f;
                for (int r = lo; r < hi; ++r) s += sMsg[col * 129 + r];
                atomicAdd(&g_dh[(size_t)ng * 128 + col], s);
            }
        }
    }
}

// node LN1 -> g_Hbuf
__global__ void __launch_bounds__(NT, 1)
node_ln_kernel(const float* __restrict__ h_V,
               const float* __restrict__ ln1_g, const float* __restrict__ ln1_b) {
    const int tid = threadIdx.x;
    const int lid = tid & 31;
    const int node = blockIdx.x * 8 + (tid >> 5);
    float4 dv = ((const float4*)(g_dh + (size_t)node * 128))[lid];
    float4 hv = ((const float4*)(h_V + (size_t)node * 128))[lid];
    float v0 = hv.x + dv.x * (1.0f / 30.0f);
    float v1 = hv.y + dv.y * (1.0f / 30.0f);
    float v2 = hv.z + dv.z * (1.0f / 30.0f);
    float v3 = hv.w + dv.w * (1.0f / 30.0f);
    float s = v0 + v1 + v2 + v3;
    float s2 = v0 * v0 + v1 * v1 + v2 * v2 + v3 * v3;
    #pragma unroll
    for (int off = 16; off > 0; off >>= 1) {
        s  += __shfl_xor_sync(0xffffffffu, s,  off);
        s2 += __shfl_xor_sync(0xffffffffu, s2, off);
    }
    float mean = s * (1.0f / 128.0f);
    float rstd = rsqrtf(s2 * (1.0f / 128.0f) - mean * mean + 1e-5f);
    float4 g = ((const float4*)ln1_g)[lid];
    float4 b = ((const float4*)ln1_b)[lid];
    float4 o;
    o.x = (v0 - mean) * rstd * g.x + b.x;
    o.y = (v1 - mean) * rstd * g.y + b.y;
    o.z = (v2 - mean) * rstd * g.z + b.z;
    o.w = (v3 - mean) * rstd * g.w + b.w;
    ((float4*)(g_Hbuf + (size_t)node * 128))[lid] = o;
}

// ---- FFN (proven fp32 f32x2) ----
#define K2_H   0
#define K2_F   4096
#define K2_O   20480
#define SM2_BYTES  (24576 * 4)
#define INNERG(J, XB, XSTRIDE, WP, WROWF)                              \
  {                                                                    \
    ulonglong2 va = __ldg((const ulonglong2*)(WP));                    \
    ulonglong2 vb = __ldg((const ulonglong2*)((WP) + (WROWF)));        \
    _Pragma("unroll")                                                  \
    for (int j = 0; j < (J); ++j) {                                    \
      u64 xa, xb; lds2(xa, xb, (XB) + j * (XSTRIDE));                  \
      fma2(acc[j][0], xa, va.x); fma2(acc[j][1], xa, va.y);            \
      fma2(acc[j][0], xb, vb.x); fma2(acc[j][1], xb, vb.y);            \
    }                                                                  \
  }

__global__ void __launch_bounds__(NT, 1)
ffn_kernel(const float* __restrict__ mask_V,
           const float* __restrict__ Win_b, const float* __restrict__ Wout_b,
           const float* __restrict__ ln2_g, const float* __restrict__ ln2_b,
           float* __restrict__ out)
{
    extern __shared__ float smf[];
    const int tid = threadIdx.x;
    const int tx  = tid & 31;
    const int ty  = tid >> 5;
    const int wm  = ty >> 1;
    const int wn  = ty & 1;
    const int m0  = wm * 8;
    const int n0  = wn * 64 + 2 * tx;
    const int nb  = blockIdx.x * 32;

    const unsigned sbase = (unsigned)__cvta_generic_to_shared(smf);
    float* sH = smf + K2_H;
    float* sF = smf + K2_F;
    float* sO = smf + K2_O;
    const float* gWin  = (const float*)g_Winp;
    const float* gWout = (const float*)g_Woutp + 2 * n0;

    {
        const float4* src = (const float4*)(g_Hbuf + (size_t)nb * Hdim);
        float4* dst = (float4*)sH;
        #pragma unroll
        for (int i = 0; i < 4; ++i) dst[i * NT + tid] = src[i * NT + tid];
    }
    __syncthreads();

    u64 acc[8][2];
    for (int nblk = 0; nblk < 4; ++nblk) {
        #pragma unroll
        for (int j = 0; j < 8; ++j) { acc[j][0] = 0ULL; acc[j][1] = 0ULL; }
        {
            const unsigned xrow = sbase + K2_H * 4 + m0 * 512;
            const float* wp = gWin + nblk * 256 + 2 * n0;
            #pragma unroll 4
            for (int it = 0; it < 32; ++it)
                INNERG(8, xrow + it * 16, 512, wp + it * 2048, 1024);
        }
        float2 bv = *(const float2*)(Win_b + nblk * 128 + n0);
        #pragma unroll
        for (int j = 0; j < 8; ++j) {
            float2 r;
            r.x = gelu_erf(hadd(acc[j][0]) + bv.x);
            r.y = gelu_erf(hadd(acc[j][1]) + bv.y);
            *(float2*)(sF + (m0 + j) * 512 + nblk * 128 + n0) = r;
        }
    }
    __syncthreads();

    #pragma unroll
    for (int j = 0; j < 8; ++j) { acc[j][0] = 0ULL; acc[j][1] = 0ULL; }
    for (int kt = 0; kt < 4; ++kt) {
        const unsigned xrow = sbase + K2_F * 4 + m0 * 2048;
        const float* wp = gWout + kt * 16384;
        #pragma unroll 4
        for (int it = 0; it < 32; ++it)
            INNERG(8, xrow + kt * 512 + it * 16, 2048, wp + it * 512, 256);
    }
    {
        float2 bv = *(const float2*)(Wout_b + n0);
        #pragma unroll
        for (int j = 0; j < 8; ++j) {
            float2 r;
            r.x = hadd(acc[j][0]) + bv.x;
            r.y = hadd(acc[j][1]) + bv.y;
            *(float2*)(sO + (m0 + j) * 128 + n0) = r;
        }
    }
    __syncthreads();

    #pragma unroll
    for (int rr = 0; rr < 4; ++rr) {
        int r = ty + rr * 8;
        float v[4];
        float s = 0.f, s2 = 0.f;
        #pragma unroll
        for (int i = 0; i < 4; ++i) {
            int n = tx + i * 32;
            v[i] = sH[r * 128 + n] + sO[r * 128 + n];
            s += v[i]; s2 += v[i] * v[i];
        }
        #pragma unroll
        for (int off = 16; off > 0; off >>= 1) {
            s  += __shfl_xor_sync(0xffffffffu, s,  off);
            s2 += __shfl_xor_sync(0xffffffffu, s2, off);
        }
        float mean = s * (1.0f / 128.0f);
        float rstd = rsqrtf(s2 * (1.0f / 128.0f) - mean * mean + 1e-5f);
        float mv = mask_V[nb + r];
        #pragma unroll
        for (int i = 0; i < 4; ++i) {
            int n = tx + i * 32;
            out[(size_t)(nb + r) * Hdim + n] =
                mv * ((v[i] - mean) * rstd * ln2_g[n] + ln2_b[n]);
        }
    }
}

extern "C" void kernel_launch(void* const* d_in, const int* in_sizes, int n_in,
                              void* d_out, int out_size) {
    const float* h_V         = (const float*)d_in[0];
    const float* h_E         = (const float*)d_in[1];
    const float* mask_V      = (const float*)d_in[2];
    const float* mask_attend = (const float*)d_in[3];
    const float* W1_w        = (const float*)d_in[4];
    const float* W1_b        = (const float*)d_in[5];
    const float* W2_w        = (const float*)d_in[6];
    const float* W2_b        = (const float*)d_in[7];
    const float* W3_w        = (const float*)d_in[8];
    const float* W3_b        = (const float*)d_in[9];
    const float* ln1_g       = (const float*)d_in[10];
    const float* ln1_b       = (const float*)d_in[11];
    const float* ln2_g       = (const float*)d_in[12];
    const float* ln2_b       = (const float*)d_in[13];
    const float* Win_w       = (const float*)d_in[14];
    const float* Win_b       = (const float*)d_in[15];
    const float* Wout_w      = (const float*)d_in[16];
    const float* Wout_b      = (const float*)d_in[17];

    int nodes = in_sizes[0] / Hdim;        // 4096
    int tiles = (nodes * KNB + 127) / 128; // 1536

    prep_weights<<<576, 256>>>(W1_w, W2_w, W3_w, Win_w, Wout_w);

    cudaFuncSetAttribute(hvc_kernel, cudaFuncAttributeMaxDynamicSharedMemorySize, 73728);
    hvc_kernel<<<nodes / 8, NT, 73728>>>(h_V, W1_w, W1_b);

    cudaFuncSetAttribute(edge_gemm_kernel, cudaFuncAttributeMaxDynamicSharedMemorySize, SM_TOT);
    edge_gemm_kernel<<<tiles, NT, SM_TOT>>>(h_E, mask_attend, W2_b, W3_b, nodes);

    node_ln_kernel<<<nodes / 8, NT>>>(h_V, ln1_g, ln1_b);

    cudaFuncSetAttribute(ffn_kernel, cudaFuncAttributeMaxDynamicSharedMemorySize, SM2_BYTES);
    ffn_kernel<<<nodes / 32, NT, SM2_BYTES>>>(mask_V, Win_b, Wout_b, ln2_g, ln2_b, (float*)d_out);
}

// round 12
// speedup vs baseline: 3.5715x; 1.3438x over previous
#include <cuda_runtime.h>
#include <cuda_bf16.h>
#include <math.h>

#define Hdim 128
#define KNB  48
#define NT   256
typedef unsigned long long u64;

__device__ __nv_bfloat16 g_W1bh[128 * 384];   // [n][k] hi
__device__ __nv_bfloat16 g_W1bl[128 * 384];
__device__ __nv_bfloat16 g_W2h[128 * 128];
__device__ __nv_bfloat16 g_W2l[128 * 128];
__device__ __nv_bfloat16 g_W3h[128 * 128];
__device__ __nv_bfloat16 g_W3l[128 * 128];
__device__ float2 g_Winp[64 * 512];
__device__ float2 g_Woutp[256 * 128];
__device__ float  g_hvc[4096 * 128];
__device__ float  g_dh[4096 * 128];
__device__ float  g_Hbuf[4096 * 128];

__device__ __forceinline__ float gelu_erf(float x) {
    return 0.5f * x * (1.0f + erff(x * 0.70710678118654752440f));
}
__device__ __forceinline__ void fma2(u64& d, u64 a, u64 b) {
    asm("fma.rn.f32x2 %0, %1, %2, %0;" : "+l"(d) : "l"(a), "l"(b));
}
__device__ __forceinline__ void lds2(u64& a, u64& b, unsigned addr) {
    asm volatile("ld.shared.v2.b64 {%0,%1}, [%2];" : "=l"(a), "=l"(b) : "r"(addr));
}
__device__ __forceinline__ float hadd(u64 p) {
    float lo, hi;
    asm("mov.b64 {%0,%1}, %2;" : "=f"(lo), "=f"(hi) : "l"(p));
    return lo + hi;
}
__device__ __forceinline__ unsigned pack2(__nv_bfloat16 a, __nv_bfloat16 b) {
    return ((unsigned)__bfloat16_as_ushort(b) << 16) | (unsigned)__bfloat16_as_ushort(a);
}
__device__ __forceinline__ void bsplit(float x, __nv_bfloat16& h, __nv_bfloat16& l) {
    h = __float2bfloat16_rn(x);
    l = __float2bfloat16_rn(x - __bfloat162float(h));
}
__device__ __forceinline__ void mma16816(float* c, const unsigned* a, const unsigned* b) {
    asm volatile(
        "mma.sync.aligned.m16n8k16.row.col.f32.bf16.bf16.f32 "
        "{%0,%1,%2,%3}, {%4,%5,%6,%7}, {%8,%9}, {%0,%1,%2,%3};"
        : "+f"(c[0]), "+f"(c[1]), "+f"(c[2]), "+f"(c[3])
        : "r"(a[0]), "r"(a[1]), "r"(a[2]), "r"(a[3]), "r"(b[0]), "r"(b[1]));
}
__device__ __forceinline__ void ldsm4(unsigned* r, unsigned addr) {
    asm volatile("ldmatrix.sync.aligned.m8n8.x4.shared.b16 {%0,%1,%2,%3}, [%4];"
        : "=r"(r[0]), "=r"(r[1]), "=r"(r[2]), "=r"(r[3]) : "r"(addr));
}

__global__ void prep_weights(const float* __restrict__ W1_w, const float* __restrict__ W2_w,
                             const float* __restrict__ W3_w, const float* __restrict__ Win_w,
                             const float* __restrict__ Wout_w) {
    int idx = blockIdx.x * blockDim.x + threadIdx.x;
    __nv_bfloat16 h, l;
    if (idx < 49152) {
        int n = idx / 384, k = idx % 384;
        bsplit(W1_w[n * 512 + 128 + k], h, l);
        g_W1bh[idx] = h; g_W1bl[idx] = l;
    } else if (idx < 65536) {
        int i = idx - 49152;
        bsplit(W2_w[i], h, l);
        g_W2h[i] = h; g_W2l[i] = l;
    } else if (idx < 81920) {
        int i = idx - 65536;
        bsplit(W3_w[i], h, l);
        g_W3h[i] = h; g_W3l[i] = l;
    } else if (idx < 114688) {
        int i = idx - 81920;
        int k2 = i >> 9, f = i & 511;
        g_Winp[i] = make_float2(Win_w[f * 128 + 2 * k2], Win_w[f * 128 + 2 * k2 + 1]);
    } else if (idx < 147456) {
        int i = idx - 114688;
        int k2 = i >> 7, n = i & 127;
        g_Woutp[i] = make_float2(Wout_w[n * 512 + 2 * k2], Wout_w[n * 512 + 2 * k2 + 1]);
    }
}

// hvc = h_V @ W1a^T + b1 (exact fp32); also zero g_dh
__global__ void __launch_bounds__(NT, 1)
hvc_kernel(const float* __restrict__ h_V, const float* __restrict__ W1_w,
           const float* __restrict__ W1_b) {
    extern __shared__ float smh[];
    float* sW  = smh;
    float* sHv = smh + 16384;
    const int tid = threadIdx.x;
    const int nb  = blockIdx.x * 8;
    #pragma unroll
    for (int i = 0; i < 16; ++i) {
        int id4 = i * NT + tid;
        int k4 = id4 >> 7, n = id4 & 127;
        float4 v = ((const float4*)(W1_w + (size_t)n * 512))[k4];
        sW[(4 * k4 + 0) * 128 + n] = v.x;
        sW[(4 * k4 + 1) * 128 + n] = v.y;
        sW[(4 * k4 + 2) * 128 + n] = v.z;
        sW[(4 * k4 + 3) * 128 + n] = v.w;
    }
    {
        int node = tid >> 5, q = tid & 31;
        float4 v = ((const float4*)(h_V + (size_t)(nb + node) * 128))[q];
        *(float4*)(sHv + node * 128 + 4 * q) = v;
        ((float4*)(g_dh + (size_t)nb * 128))[tid] = make_float4(0.f, 0.f, 0.f, 0.f);
    }
    __syncthreads();
    #pragma unroll
    for (int it = 0; it < 4; ++it) {
        int o = it * NT + tid;
        int node = o >> 7, col = o & 127;
        const float* hv = sHv + node * 128;
        float a = W1_b[col];
        #pragma unroll 8
        for (int k = 0; k < 128; ++k) a = fmaf(hv[k], sW[k * 128 + col], a);
        g_hvc[(size_t)(nb + node) * 128 + col] = a;
    }
}

// ---- edge GEMM smem layout; chunk = [128 rows][36 b32] = 18432 B (144B rows, 16B aligned) ----
#define CHB     18432
#define CHW     (CHB / 4)
#define SM_BIAS 0
#define SM_HVC  1024
#define SM_Y1   3072                    // 4 chunks (c0h,c0l,c1h,c1l)
#define SM_X    (SM_Y1 + 4 * CHB)       // GEMM1 A stage (h,l); later Y2 (4 chunks)
#define SM_B    (SM_X + 4 * CHB)        // B stage (h,l)
#define SM_TOT  (SM_B + 2 * CHB)        // 187392

__device__ __forceinline__ void stage_B(char* smem, const __nv_bfloat16* gh,
                                        const __nv_bfloat16* gl, int K, int c, int tid) {
    unsigned* dh = (unsigned*)(smem + SM_B);
    unsigned* dl = dh + CHW;
    #pragma unroll
    for (int i = 0; i < 4; ++i) {
        int idx = i * NT + tid;
        int n = idx >> 3, q = idx & 7;
        uint4 vh = *(const uint4*)(gh + (size_t)n * K + c * 64 + q * 8);
        uint4 vl = *(const uint4*)(gl + (size_t)n * K + c * 64 + q * 8);
        int o = n * 36 + q * 4;
        *(uint4*)(dh + o) = vh;
        *(uint4*)(dl + o) = vl;
    }
}

// one 64k chunk: acc[64] += A(128x64) * B^T, split-bf16 (hh+hl+lh), ldmatrix operands
__device__ __forceinline__ void chunk_mma(unsigned sAh, unsigned sAl,
                                          unsigned sBh, unsigned sBl,
                                          float* acc, unsigned aoff, unsigned boff) {
    #pragma unroll
    for (int v = 0; v < 2; ++v) {
        unsigned ah[2][2][4], al[2][2][4];
        #pragma unroll
        for (int t = 0; t < 2; ++t)
            #pragma unroll
            for (int sl = 0; sl < 2; ++sl) {
                unsigned off = aoff + t * 2304 + (2 * v + sl) * 32;
                ldsm4(ah[t][sl], sAh + off);
                ldsm4(al[t][sl], sAl + off);
            }
        #pragma unroll
        for (int u = 0; u < 8; ++u) {
            unsigned bh4[4], bl4[4];
            unsigned off = boff + u * 1152 + v * 64;
            ldsm4(bh4, sBh + off);
            ldsm4(bl4, sBl + off);
            #pragma unroll
            for (int t = 0; t < 2; ++t) {
                float* cc = acc + (t * 8 + u) * 4;
                #pragma unroll
                for (int sl = 0; sl < 2; ++sl) {
                    mma16816(cc, ah[t][sl], bh4 + 2 * sl);
                    mma16816(cc, ah[t][sl], bl4 + 2 * sl);
                    mma16816(cc, al[t][sl], bh4 + 2 * sl);
                }
            }
        }
    }
}

__global__ void __launch_bounds__(NT, 1)
edge_gemm_kernel(const float* __restrict__ h_E, const float* __restrict__ mask_attend,
                 const float* __restrict__ W2_b, const float* __restrict__ W3_b,
                 int n_nodes) {
    extern __shared__ char smem[];
    const int tid = threadIdx.x;
    const int wid = tid >> 5;
    const int lane = tid & 31;
    const int g = lane >> 2, t4 = lane & 3;
    const int wm = wid >> 1, wn = wid & 1;
    const int m0 = wm * 32, nb0 = wn * 64;
    const int base = blockIdx.x * 128;
    const int n0 = base / 48;
    const unsigned sb = (unsigned)__cvta_generic_to_shared(smem);

    // ldmatrix per-lane address offsets (bytes, relative to chunk base)
    const unsigned aoff = (m0 + (lane & 15)) * 144 + (lane >> 4) * 16;
    const unsigned boff = (nb0 + (lane & 7)) * 144 + (lane >> 3) * 16;

    if (tid < 128) {
        ((float*)(smem + SM_BIAS))[tid]       = W2_b[tid];
        ((float*)(smem + SM_BIAS))[128 + tid] = W3_b[tid];
    }
    for (int t = tid; t < 512; t += NT) {
        int gg = t >> 7, c = t & 127;
        int nd = n0 + gg;
        ((float*)(smem + SM_HVC))[t] = (nd < n_nodes) ? g_hvc[(size_t)nd * 128 + c] : 0.f;
    }

    float acc[64];
    #pragma unroll
    for (int i = 0; i < 64; ++i) acc[i] = 0.f;

    // ---------- GEMM1: h_E @ W1b^T, K=384 ----------
    for (int c = 0; c < 6; ++c) {
        __syncthreads();
        {
            unsigned* dh = (unsigned*)(smem + SM_X);
            unsigned* dl = dh + CHW;
            #pragma unroll
            for (int i = 0; i < 4; ++i) {
                int idx = i * NT + tid;
                int r = idx >> 3, q = idx & 7;
                const float4* p = (const float4*)(h_E + (size_t)(base + r) * 384 + c * 64 + q * 8);
                float4 v0 = p[0], v1 = p[1];
                float f[8] = {v0.x, v0.y, v0.z, v0.w, v1.x, v1.y, v1.z, v1.w};
                __nv_bfloat16 hb[8], lb[8];
                #pragma unroll
                for (int j = 0; j < 8; ++j) bsplit(f[j], hb[j], lb[j]);
                int o = r * 36 + q * 4;
                uint4 uh, ul;
                uh.x = pack2(hb[0], hb[1]); uh.y = pack2(hb[2], hb[3]);
                uh.z = pack2(hb[4], hb[5]); uh.w = pack2(hb[6], hb[7]);
                ul.x = pack2(lb[0], lb[1]); ul.y = pack2(lb[2], lb[3]);
                ul.z = pack2(lb[4], lb[5]); ul.w = pack2(lb[6], lb[7]);
                *(uint4*)(dh + o) = uh;
                *(uint4*)(dl + o) = ul;
            }
        }
        stage_B(smem, g_W1bh, g_W1bl, 384, c, tid);
        __syncthreads();
        chunk_mma(sb + SM_X, sb + SM_X + CHB, sb + SM_B, sb + SM_B + CHB, acc, aoff, boff);
    }
    __syncthreads();
    // epilogue 1: y1 = gelu(D + hvc[node]) -> Y1 chunks (bf16 hi/lo)
    {
        const float* hvc = (const float*)(smem + SM_HVC);
        unsigned* y = (unsigned*)(smem + SM_Y1);
        #pragma unroll
        for (int t = 0; t < 2; ++t) {
            int r1 = m0 + t * 16 + g, r2 = r1 + 8;
            int h1 = (base + r1) / 48 - n0, h2 = (base + r2) / 48 - n0;
            #pragma unroll
            for (int u = 0; u < 8; ++u) {
                int n = nb0 + u * 8 + 2 * t4;
                const float* cc = acc + (t * 8 + u) * 4;
                float ya = gelu_erf(cc[0] + hvc[h1 * 128 + n]);
                float yb = gelu_erf(cc[1] + hvc[h1 * 128 + n + 1]);
                float yc = gelu_erf(cc[2] + hvc[h2 * 128 + n]);
                float yd = gelu_erf(cc[3] + hvc[h2 * 128 + n + 1]);
                __nv_bfloat16 ha, la, hb, lb, hc, lc, hd, ld;
                bsplit(ya, ha, la); bsplit(yb, hb, lb);
                bsplit(yc, hc, lc); bsplit(yd, hd, ld);
                int ch = n >> 6, col = (n & 63) >> 1;
                unsigned* yh = y + (2 * ch) * CHW;
                unsigned* yl = y + (2 * ch + 1) * CHW;
                yh[r1 * 36 + col] = pack2(ha, hb);
                yl[r1 * 36 + col] = pack2(la, lb);
                yh[r2 * 36 + col] = pack2(hc, hd);
                yl[r2 * 36 + col] = pack2(lc, ld);
            }
        }
    }
    #pragma unroll
    for (int i = 0; i < 64; ++i) acc[i] = 0.f;
    __syncthreads();

    // ---------- GEMM2: Y1 @ W2^T, K=128 ----------
    for (int c = 0; c < 2; ++c) {
        stage_B(smem, g_W2h, g_W2l, 128, c, tid);
        __syncthreads();
        chunk_mma(sb + SM_Y1 + (2 * c) * CHB, sb + SM_Y1 + (2 * c + 1) * CHB,
                  sb + SM_B, sb + SM_B + CHB, acc, aoff, boff);
        __syncthreads();
    }
    // epilogue 2: y2 = gelu(D + b2) -> X region chunks
    {
        const float* b2 = (const float*)(smem + SM_BIAS);
        unsigned* y = (unsigned*)(smem + SM_X);
        #pragma unroll
        for (int t = 0; t < 2; ++t) {
            int r1 = m0 + t * 16 + g, r2 = r1 + 8;
            #pragma unroll
            for (int u = 0; u < 8; ++u) {
                int n = nb0 + u * 8 + 2 * t4;
                const float* cc = acc + (t * 8 + u) * 4;
                float ya = gelu_erf(cc[0] + b2[n]);
                float yb = gelu_erf(cc[1] + b2[n + 1]);
                float yc = gelu_erf(cc[2] + b2[n]);
                float yd = gelu_erf(cc[3] + b2[n + 1]);
                __nv_bfloat16 ha, la, hb, lb, hc, lc, hd, ld;
                bsplit(ya, ha, la); bsplit(yb, hb, lb);
                bsplit(yc, hc, lc); bsplit(yd, hd, ld);
                int ch = n >> 6, col = (n & 63) >> 1;
                unsigned* yh = y + (2 * ch) * CHW;
                unsigned* yl = y + (2 * ch + 1) * CHW;
                yh[r1 * 36 + col] = pack2(ha, hb);
                yl[r1 * 36 + col] = pack2(la, lb);
                yh[r2 * 36 + col] = pack2(hc, hd);
                yl[r2 * 36 + col] = pack2(lc, ld);
            }
        }
    }
    #pragma unroll
    for (int i = 0; i < 64; ++i) acc[i] = 0.f;
    __syncthreads();

    // ---------- GEMM3: Y2 @ W3^T, K=128 ----------
    for (int c = 0; c < 2; ++c) {
        stage_B(smem, g_W3h, g_W3l, 128, c, tid);
        __syncthreads();
        chunk_mma(sb + SM_X + (2 * c) * CHB, sb + SM_X + (2 * c + 1) * CHB,
                  sb + SM_B, sb + SM_B + CHB, acc, aoff, boff);
        __syncthreads();
    }
    // epilogue 3: msg = (D + b3) * mask -> sMsg [n][129]; segment sums -> g_dh
    {
        const float* b3 = (const float*)(smem + SM_BIAS) + 128;
        float* sMsg = (float*)(smem + SM_Y1);
        #pragma unroll
        for (int t = 0; t < 2; ++t) {
            int r1 = m0 + t * 16 + g, r2 = r1 + 8;
            float mk1 = mask_attend[base + r1];
            float mk2 = mask_attend[base + r2];
            #pragma unroll
            for (int u = 0; u < 8; ++u) {
                int n = nb0 + u * 8 + 2 * t4;
                const float* cc = acc + (t * 8 + u) * 4;
                sMsg[n * 129 + r1]       = (cc[0] + b3[n])     * mk1;
                sMsg[(n + 1) * 129 + r1] = (cc[1] + b3[n + 1]) * mk1;
                sMsg[n * 129 + r2]       = (cc[2] + b3[n])     * mk2;
                sMsg[(n + 1) * 129 + r2] = (cc[3] + b3[n + 1]) * mk2;
            }
        }
    }
    __syncthreads();
    if (tid < 128) {
        const float* sMsg = (const float*)(smem + SM_Y1);
        int col = tid;
        #pragma unroll
        for (int gg = 0; gg < 4; ++gg) {
            int ng = n0 + gg;
            if (ng >= n_nodes) break;
            int lo = ng * 48 - base, hi = lo + 48;
            if (lo < 0) lo = 0;
            if (hi > 128) hi = 128;
            if (lo < hi) {
                float s = 0.f;
                for (int r = lo; r < hi; ++r) s += sMsg[col * 129 + r];
                atomicAdd(&g_dh[(size_t)ng * 128 + col], s);
            }
        }
    }
}

// node LN1 -> g_Hbuf
__global__ void __launch_bounds__(NT, 1)
node_ln_kernel(const float* __restrict__ h_V,
               const float* __restrict__ ln1_g, const float* __restrict__ ln1_b) {
    const int tid = threadIdx.x;
    const int lid = tid & 31;
    const int node = blockIdx.x * 8 + (tid >> 5);
    float4 dv = ((const float4*)(g_dh + (size_t)node * 128))[lid];
    float4 hv = ((const float4*)(h_V + (size_t)node * 128))[lid];
    float v0 = hv.x + dv.x * (1.0f / 30.0f);
    float v1 = hv.y + dv.y * (1.0f / 30.0f);
    float v2 = hv.z + dv.z * (1.0f / 30.0f);
    float v3 = hv.w + dv.w * (1.0f / 30.0f);
    float s = v0 + v1 + v2 + v3;
    float s2 = v0 * v0 + v1 * v1 + v2 * v2 + v3 * v3;
    #pragma unroll
    for (int off = 16; off > 0; off >>= 1) {
        s  += __shfl_xor_sync(0xffffffffu, s,  off);
        s2 += __shfl_xor_sync(0xffffffffu, s2, off);
    }
    float mean = s * (1.0f / 128.0f);
    float rstd = rsqrtf(s2 * (1.0f / 128.0f) - mean * mean + 1e-5f);
    float4 g = ((const float4*)ln1_g)[lid];
    float4 b = ((const float4*)ln1_b)[lid];
    float4 o;
    o.x = (v0 - mean) * rstd * g.x + b.x;
    o.y = (v1 - mean) * rstd * g.y + b.y;
    o.z = (v2 - mean) * rstd * g.z + b.z;
    o.w = (v3 - mean) * rstd * g.w + b.w;
    ((float4*)(g_Hbuf + (size_t)node * 128))[lid] = o;
}

// ---- FFN (proven fp32 f32x2) ----
#define K2_H   0
#define K2_F   4096
#define K2_O   20480
#define SM2_BYTES  (24576 * 4)
#define INNERG(J, XB, XSTRIDE, WP, WROWF)                              \
  {                                                                    \
    ulonglong2 va = __ldg((const ulonglong2*)(WP));                    \
    ulonglong2 vb = __ldg((const ulonglong2*)((WP) + (WROWF)));        \
    _Pragma("unroll")                                                  \
    for (int j = 0; j < (J); ++j) {                                    \
      u64 xa, xb; lds2(xa, xb, (XB) + j * (XSTRIDE));                  \
      fma2(acc[j][0], xa, va.x); fma2(acc[j][1], xa, va.y);            \
      fma2(acc[j][0], xb, vb.x); fma2(acc[j][1], xb, vb.y);            \
    }                                                                  \
  }

__global__ void __launch_bounds__(NT, 1)
ffn_kernel(const float* __restrict__ mask_V,
           const float* __restrict__ Win_b, const float* __restrict__ Wout_b,
           const float* __restrict__ ln2_g, const float* __restrict__ ln2_b,
           float* __restrict__ out)
{
    extern __shared__ float smf[];
    const int tid = threadIdx.x;
    const int tx  = tid & 31;
    const int ty  = tid >> 5;
    const int wm  = ty >> 1;
    const int wn  = ty & 1;
    const int m0  = wm * 8;
    const int n0  = wn * 64 + 2 * tx;
    const int nb  = blockIdx.x * 32;

    const unsigned sbase = (unsigned)__cvta_generic_to_shared(smf);
    float* sH = smf + K2_H;
    float* sF = smf + K2_F;
    float* sO = smf + K2_O;
    const float* gWin  = (const float*)g_Winp;
    const float* gWout = (const float*)g_Woutp + 2 * n0;

    {
        const float4* src = (const float4*)(g_Hbuf + (size_t)nb * Hdim);
        float4* dst = (float4*)sH;
        #pragma unroll
        for (int i = 0; i < 4; ++i) dst[i * NT + tid] = src[i * NT + tid];
    }
    __syncthreads();

    u64 acc[8][2];
    for (int nblk = 0; nblk < 4; ++nblk) {
        #pragma unroll
        for (int j = 0; j < 8; ++j) { acc[j][0] = 0ULL; acc[j][1] = 0ULL; }
        {
            const unsigned xrow = sbase + K2_H * 4 + m0 * 512;
            const float* wp = gWin + nblk * 256 + 2 * n0;
            #pragma unroll 4
            for (int it = 0; it < 32; ++it)
                INNERG(8, xrow + it * 16, 512, wp + it * 2048, 1024);
        }
        float2 bv = *(const float2*)(Win_b + nblk * 128 + n0);
        #pragma unroll
        for (int j = 0; j < 8; ++j) {
            float2 r;
            r.x = gelu_erf(hadd(acc[j][0]) + bv.x);
            r.y = gelu_erf(hadd(acc[j][1]) + bv.y);
            *(float2*)(sF + (m0 + j) * 512 + nblk * 128 + n0) = r;
        }
    }
    __syncthreads();

    #pragma unroll
    for (int j = 0; j < 8; ++j) { acc[j][0] = 0ULL; acc[j][1] = 0ULL; }
    for (int kt = 0; kt < 4; ++kt) {
        const unsigned xrow = sbase + K2_F * 4 + m0 * 2048;
        const float* wp = gWout + kt * 16384;
        #pragma unroll 4
        for (int it = 0; it < 32; ++it)
            INNERG(8, xrow + kt * 512 + it * 16, 2048, wp + it * 512, 256);
    }
    {
        float2 bv = *(const float2*)(Wout_b + n0);
        #pragma unroll
        for (int j = 0; j < 8; ++j) {
            float2 r;
            r.x = hadd(acc[j][0]) + bv.x;
            r.y = hadd(acc[j][1]) + bv.y;
            *(float2*)(sO + (m0 + j) * 128 + n0) = r;
        }
    }
    __syncthreads();

    #pragma unroll
    for (int rr = 0; rr < 4; ++rr) {
        int r = ty + rr * 8;
        float v[4];
        float s = 0.f, s2 = 0.f;
        #pragma unroll
        for (int i = 0; i < 4; ++i) {
            int n = tx + i * 32;
            v[i] = sH[r * 128 + n] + sO[r * 128 + n];
            s += v[i]; s2 += v[i] * v[i];
        }
        #pragma unroll
        for (int off = 16; off > 0; off >>= 1) {
            s  += __shfl_xor_sync(0xffffffffu, s,  off);
            s2 += __shfl_xor_sync(0xffffffffu, s2, off);
        }
        float mean = s * (1.0f / 128.0f);
        float rstd = rsqrtf(s2 * (1.0f / 128.0f) - mean * mean + 1e-5f);
        float mv = mask_V[nb + r];
        #pragma unroll
        for (int i = 0; i < 4; ++i) {
            int n = tx + i * 32;
            out[(size_t)(nb + r) * Hdim + n] =
                mv * ((v[i] - mean) * rstd * ln2_g[n] + ln2_b[n]);
        }
    }
}

extern "C" void kernel_launch(void* const* d_in, const int* in_sizes, int n_in,
                              void* d_out, int out_size) {
    const float* h_V         = (const float*)d_in[0];
    const float* h_E         = (const float*)d_in[1];
    const float* mask_V      = (const float*)d_in[2];
    const float* mask_attend = (const float*)d_in[3];
    const float* W1_w        = (const float*)d_in[4];
    const float* W1_b        = (const float*)d_in[5];
    const float* W2_w        = (const float*)d_in[6];
    const float* W2_b        = (const float*)d_in[7];
    const float* W3_w        = (const float*)d_in[8];
    const float* W3_b        = (const float*)d_in[9];
    const float* ln1_g       = (const float*)d_in[10];
    const float* ln1_b       = (const float*)d_in[11];
    const float* ln2_g       = (const float*)d_in[12];
    const float* ln2_b       = (const float*)d_in[13];
    const float* Win_w       = (const float*)d_in[14];
    const float* Win_b       = (const float*)d_in[15];
    const float* Wout_w      = (const float*)d_in[16];
    const float* Wout_b      = (const float*)d_in[17];

    int nodes = in_sizes[0] / Hdim;        // 4096
    int tiles = (nodes * KNB + 127) / 128; // 1536

    prep_weights<<<576, 256>>>(W1_w, W2_w, W3_w, Win_w, Wout_w);

    cudaFuncSetAttribute(hvc_kernel, cudaFuncAttributeMaxDynamicSharedMemorySize, 73728);
    hvc_kernel<<<nodes / 8, NT, 73728>>>(h_V, W1_w, W1_b);

    cudaFuncSetAttribute(edge_gemm_kernel, cudaFuncAttributeMaxDynamicSharedMemorySize, SM_TOT);
    edge_gemm_kernel<<<tiles, NT, SM_TOT>>>(h_E, mask_attend, W2_b, W3_b, nodes);

    node_ln_kernel<<<nodes / 8, NT>>>(h_V, ln1_g, ln1_b);

    cudaFuncSetAttribute(ffn_kernel, cudaFuncAttributeMaxDynamicSharedMemorySize, SM2_BYTES);
    ffn_kernel<<<nodes / 32, NT, SM2_BYTES>>>(mask_V, Win_b, Wout_b, ln2_g, ln2_b, (float*)d_out);
}